// round 8
// baseline (speedup 1.0000x reference)
#include <cuda_runtime.h>
#include <math.h>
#include <stdint.h>

// ---------------- problem constants ----------------
#define N_R     2000
#define N_P     1512
#define MROWS   3512            // N_R + N_P
#define SIZE_R  3000
#define FUN_IN  5603
#define NB      8192            // batch of pairs
#define PROTEIN 1512

// d_out layout: e_r [2000,512] | e_p [1512,512] | output [8192,2] | flat [8192,8192]
#define E_P_OFF   1024000
#define OUT_OFF   1798144
#define FLAT_OFF  1814528

#define SPLITK 4

// smem strides (words)
#define ASTR 24     // As row stride: conflict-free 64-bit frag loads (12g+t perm mod 16)
#define BSTR 132    // Bs row stride: 132%32=4 -> rows {2t},{2t+1} conflict-free 32-bit loads

// ---------------- device scratch (no allocs allowed) ----------------
__device__ float g_h_att[MROWS * 2048];
__device__ float g_h_fun[MROWS * 4096];
__device__ float g_e[MROWS * 512];
__device__ float g_part[SPLITK * MROWS * 256];

// ---------------- helpers ----------------
typedef unsigned long long ull;

__device__ __forceinline__ void mma_tf32(float c[4],
    uint32_t a0, uint32_t a1, uint32_t a2, uint32_t a3,
    uint32_t b0, uint32_t b1)
{
    asm volatile(
        "mma.sync.aligned.m16n8k8.row.col.f32.tf32.tf32.f32 "
        "{%0,%1,%2,%3}, {%4,%5,%6,%7}, {%8,%9}, {%0,%1,%2,%3};\n"
        : "+f"(c[0]), "+f"(c[1]), "+f"(c[2]), "+f"(c[3])
        : "r"(a0), "r"(a1), "r"(a2), "r"(a3), "r"(b0), "r"(b1));
}

__device__ __forceinline__ void cp16(uint32_t dst, const void* src, int srcBytes) {
    asm volatile("cp.async.cg.shared.global [%0], [%1], 16, %2;\n"
                 :: "r"(dst), "l"(src), "r"(srcBytes));
}
__device__ __forceinline__ void cp4(uint32_t dst, const void* src, int srcBytes) {
    asm volatile("cp.async.ca.shared.global [%0], [%1], 4, %2;\n"
                 :: "r"(dst), "l"(src), "r"(srcBytes));
}
__device__ __forceinline__ void cp_commit() {
    asm volatile("cp.async.commit_group;\n" ::);
}
template<int W> __device__ __forceinline__ void cp_wait() {
    asm volatile("cp.async.wait_group %0;\n" :: "n"(W));
}

__device__ __forceinline__ ull pk(float lo, float hi) {
    ull r; asm("mov.b64 %0, {%1, %2};" : "=l"(r) : "f"(lo), "f"(hi)); return r;
}
__device__ __forceinline__ void upk(ull v, float& lo, float& hi) {
    asm("mov.b64 {%0, %1}, %2;" : "=f"(lo), "=f"(hi) : "l"(v));
}
__device__ __forceinline__ ull fma2(ull a, ull b, ull c) {
    ull d; asm("fma.rn.f32x2 %0, %1, %2, %3;" : "=l"(d) : "l"(a), "l"(b), "l"(c)); return d;
}

// ---------------- TF32 tensor-core GEMM, 3-stage cp.async pipeline ----------------
// Logical-k permutation: logical t <-> physical 2t, logical t+4 <-> physical 2t+1.
// Same permutation applied to A and B fragment reads => GEMM result unchanged,
// A-fragments become 64-bit v2 loads (halves A LDS instruction count).
// MODE 0: gelu(exact) -> C[r*ldc + c], full K.
// MODE 2: raw partial -> C + blockIdx.z*M*256, K slice [z*ksl, min(K,(z+1)*ksl)).
template<int BM, int MODE, bool ALIGNED>
__global__ void __launch_bounds__(256, 2) mma_gemm(
    const float* __restrict__ A0, const float* __restrict__ A1, int split,
    int M, int N, int K, int lda,
    const float* __restrict__ B, const float* __restrict__ bias,
    float* __restrict__ C, int ldc, int ksl)
{
    constexpr int BN = 128;
    constexpr int BK = 16;
    constexpr int MT = BM / 32;
    constexpr int AF = (BM * BK) / (4 * 256);

    extern __shared__ uint32_t smemU[];
    uint32_t* As = smemU;                      // [3][BM][ASTR]
    uint32_t* Bs = smemU + 3 * BM * ASTR;      // [3][BK][BSTR]

    const int tid  = threadIdx.x;
    const int lane = tid & 31;
    const int warp = tid >> 5;
    const int wr = warp & 1;
    const int wc = warp >> 1;
    const int g = lane >> 2;
    const int t = lane & 3;

    const int rowBase = blockIdx.y * BM;
    const int colBase = blockIdx.x * BN;
    const int wm = wr * (BM / 2);
    const int wn = wc * 32;

    int kbeg = 0, kend = K;
    if (MODE == 2) { kbeg = blockIdx.z * ksl; kend = min(K, kbeg + ksl); }
    float* Cp = C;
    if (MODE == 2) Cp = C + (size_t)blockIdx.z * M * 256;

    float acc[MT][4][4];
#pragma unroll
    for (int i = 0; i < MT; i++)
#pragma unroll
        for (int j = 0; j < 4; j++)
#pragma unroll
            for (int q = 0; q < 4; q++) acc[i][j][q] = 0.0f;

    const float* Arow[AF];
#pragma unroll
    for (int i = 0; i < AF; i++) {
        int f = tid + i * 256;
        int m = f >> 2;
        int row = rowBase + m;
        Arow[i] = 0;
        if (row < M)
            Arow[i] = (row < split) ? (A0 + (size_t)row * lda)
                                    : (A1 + (size_t)(row - split) * lda);
    }

    const uint32_t AsAddr = (uint32_t)__cvta_generic_to_shared(As);
    const uint32_t BsAddr = (uint32_t)__cvta_generic_to_shared(Bs);

    const int nIter = (kend - kbeg + BK - 1) / BK;

    auto issueTile = [&](int it, int buf) {
        int k0 = kbeg + it * BK;
#pragma unroll
        for (int i = 0; i < AF; i++) {
            int f = tid + i * 256;
            int m = f >> 2;
            int kq = f & 3;
            int k = k0 + kq * 4;
            uint32_t dst = AsAddr + (uint32_t)((((buf * BM + m) * ASTR) + kq * 4) * 4);
            if (ALIGNED) {
                int bytes = 0;
                if (Arow[i]) { bytes = (kend - k) * 4; bytes = bytes < 0 ? 0 : (bytes > 16 ? 16 : bytes); }
                cp16(dst, Arow[i] ? (Arow[i] + k) : A0, bytes);
            } else {
#pragma unroll
                for (int j = 0; j < 4; j++) {
                    int bytes = (Arow[i] && (k + j) < kend) ? 4 : 0;
                    cp4(dst + 4 * j, Arow[i] ? (Arow[i] + k + j) : A0, bytes);
                }
            }
        }
#pragma unroll
        for (int i = 0; i < 2; i++) {
            int f = tid + i * 256;
            int kk = f >> 5;
            int nq = f & 31;
            int krow = k0 + kk;
            uint32_t dst = BsAddr + (uint32_t)((((buf * BK + kk) * BSTR) + nq * 4) * 4);
            int kc = krow < K - 1 ? krow : K - 1;
            const float* src = B + (size_t)kc * N + colBase + nq * 4;
            cp16(dst, src, krow < kend ? 16 : 0);
        }
        cp_commit();
    };

    issueTile(0, 0);
    if (nIter > 1) issueTile(1, 1);

    int buf = 0;
    for (int it = 0; it < nIter; it++) {
        if (it + 1 < nIter) cp_wait<1>(); else cp_wait<0>();
        __syncthreads();

#pragma unroll
        for (int ks = 0; ks < 2; ks++) {
            uint32_t afr[MT][4];
            uint32_t bfr[4][2];
#pragma unroll
            for (int mt = 0; mt < MT; mt++) {
                int r0 = wm + mt * 16 + g;
                const uint32_t* pa = As + (buf * BM + r0) * ASTR + ks * 8 + 2 * t;
                uint2 va = *(const uint2*)pa;             // row r0:   (log k=t, k=t+4)
                uint2 vb = *(const uint2*)(pa + 8 * ASTR);// row r0+8: (log k=t, k=t+4)
                afr[mt][0] = va.x;
                afr[mt][1] = vb.x;
                afr[mt][2] = va.y;
                afr[mt][3] = vb.y;
            }
#pragma unroll
            for (int nt = 0; nt < 4; nt++) {
                int c0 = wn + nt * 8 + g;
                const uint32_t* pb = Bs + (buf * BK + ks * 8 + 2 * t) * BSTR + c0;
                bfr[nt][0] = pb[0];        // phys row 2t   -> logical k=t
                bfr[nt][1] = pb[BSTR];     // phys row 2t+1 -> logical k=t+4
            }
#pragma unroll
            for (int mt = 0; mt < MT; mt++)
#pragma unroll
                for (int nt = 0; nt < 4; nt++)
                    mma_tf32(acc[mt][nt],
                             afr[mt][0], afr[mt][1], afr[mt][2], afr[mt][3],
                             bfr[nt][0], bfr[nt][1]);
        }
        __syncthreads();

        if (it + 2 < nIter) issueTile(it + 2, (it + 2) % 3);
        buf = (buf + 1 == 3) ? 0 : buf + 1;
    }

    // ---- epilogue ----
#pragma unroll
    for (int mt = 0; mt < MT; mt++) {
#pragma unroll
        for (int rh = 0; rh < 2; rh++) {
            int r = rowBase + wm + mt * 16 + g + rh * 8;
            if (r >= M) continue;
#pragma unroll
            for (int nt = 0; nt < 4; nt++) {
#pragma unroll
                for (int cj = 0; cj < 2; cj++) {
                    int c = colBase + wn + nt * 8 + 2 * t + cj;
                    if (c >= N) continue;
                    float v = acc[mt][nt][rh * 2 + cj];
                    if (MODE == 0) {
                        v += bias[c];
                        v = 0.5f * v * (1.0f + erff(v * 0.70710678118654752f));
                        C[(size_t)r * ldc + c] = v;
                    } else {
                        Cp[(size_t)r * 256 + c] = v;
                    }
                }
            }
        }
    }
}

// dynamic smem bytes for mma_gemm<BM,...>
static inline int gemm_smem_bytes(int BM) {
    return (3 * BM * ASTR + 3 * 16 * BSTR) * 4;
}

// ---------------- split-K reduce + bias + sigmoid + scatter ----------------
__global__ void __launch_bounds__(256) splitk_epilogue(
    const float* __restrict__ part, const float* __restrict__ bias,
    float* __restrict__ ebuf, float* __restrict__ dout, int ecol)
{
    int i = blockIdx.x * 256 + threadIdx.x;       // over MROWS*256
    int r = i >> 8;
    int c = i & 255;
    if (r >= MROWS) return;
    float v = part[i];
#pragma unroll
    for (int s = 1; s < SPLITK; s++) v += part[i + (size_t)s * MROWS * 256];
    v = 1.0f / (1.0f + expf(-(v + bias[c])));
    ebuf[(size_t)r * 512 + ecol + c] = v;
    if (r < N_R)
        dout[(size_t)r * 512 + ecol + c] = v;
    else
        dout[(size_t)E_P_OFF + (size_t)(r - N_R) * 512 + ecol + c] = v;
}

// ---------------- pair kernel ----------------
#define SM_XP    0
#define SM_H1P   3120
#define SM_SW2   (3120 + 8448)
#define SM_SW1   (3120 + 8448 + 7680)
#define SM_BRED  (3120 + 8448 + 7680 + 240)
#define SM_TOTAL (3120 + 8448 + 7680 + 240 + 16)

template<int S, int RR, int IH>
__device__ __forceinline__ void combo(
    ull accp[2][2][4], const ull wp[2][2][5], const ull hp[2][11])
{
#pragma unroll
    for (int jp = 0; jp < 4; jp++)
#pragma unroll
        for (int kw = 0; kw < 5; kw++) {
            accp[0][RR][jp] = fma2(wp[0][S][kw], hp[IH][2 * jp + kw], accp[0][RR][jp]);
            accp[1][RR][jp] = fma2(wp[1][S][kw], hp[IH][2 * jp + kw], accp[1][RR][jp]);
        }
}

__global__ void __launch_bounds__(256) pair_kernel(
    const float* __restrict__ e, const int* __restrict__ idx,
    const float* __restrict__ w1, const float* __restrict__ b1,
    const float* __restrict__ w2, const float* __restrict__ b2,
    const float* __restrict__ Wout, const float* __restrict__ bout,
    float* __restrict__ dout)
{
    extern __shared__ float sm[];
    float* xp   = sm + SM_XP;    // [6][520]
    float* h1p  = sm + SM_H1P;   // [16][2][264]
    float* sw2  = sm + SM_SW2;   // [32][16][15]
    float* sw1  = sm + SM_SW1;   // [16][15]
    float* bred = sm + SM_BRED;  // [16]

    const int tid = threadIdx.x;
    const int b = blockIdx.x;

    const int iv = idx[b];
    const int rno = iv / PROTEIN;
    const int pno = iv % PROTEIN;
    const float* er = e + (size_t)rno * 512;
    const float* ep = e + (size_t)(N_R + pno) * 512;

    for (int i = tid; i < 6 * 520; i += 256) xp[i] = 0.0f;
    for (int i = tid; i < 16 * 2 * 264; i += 256) h1p[i] = 0.0f;
    for (int i = tid; i < 240; i += 256) sw1[i] = w1[i];
    for (int i = tid; i < 7680; i += 256) sw2[i] = w2[i];
    for (int w = tid; w < 512; w += 256) {
        xp[2 * 520 + 4 + w] = er[w];
        xp[3 * 520 + 4 + w] = ep[w];
    }
    __syncthreads();

    // conv1 + leaky + avgpool
    for (int id = tid; id < 16 * 2 * 256; id += 256) {
        int c  = id >> 9;
        int rm = id & 511;
        int ph = rm >> 8;
        int pw = rm & 255;
        float wv[15];
#pragma unroll
        for (int q = 0; q < 15; q++) wv[q] = sw1[c * 15 + q];
        float bb = b1[c];
        float sum = 0.0f;
#pragma unroll
        for (int oh2 = 0; oh2 < 2; oh2++) {
#pragma unroll
            for (int ow2 = 0; ow2 < 2; ow2++) {
                int oh = 2 * ph + oh2;
                int ow = 2 * pw + ow2;
                float v = bb;
#pragma unroll
                for (int kh = 0; kh < 3; kh++) {
                    const float* xr = xp + (oh + kh) * 520 + (ow + 2);
#pragma unroll
                    for (int kw = 0; kw < 5; kw++)
                        v = fmaf(wv[kh * 5 + kw], xr[kw], v);
                }
                sum += (v >= 0.0f) ? v : 0.01f * v;
            }
        }
        h1p[(c * 2 + ph) * 264 + 4 + pw] = 0.25f * sum;
    }
    __syncthreads();

    // conv2 (f32x2 packed) + leaky + maxpool + tanh + flat + W_out dot
    float a0 = 0.0f, a1 = 0.0f;

    for (int tt = 0; tt < 4; tt++) {
        int task = tt * 256 + tid;
        int ocp = task >> 6;
        int ph  = (task >> 5) & 1;
        int pwg = task & 31;
        int oc0 = ocp * 2;
        int w0 = pwg * 8;

        ull accp[2][2][4];
#pragma unroll
        for (int o = 0; o < 2; o++)
#pragma unroll
            for (int r = 0; r < 2; r++)
#pragma unroll
                for (int jp = 0; jp < 4; jp++) accp[o][r][jp] = 0ull;

        const int khA = ph ? 0 : 1;   // needed kh rows: {khA, khA+1}

        for (int ic = 0; ic < 16; ic++) {
            ull hp[2][11];
#pragma unroll
            for (int ih = 0; ih < 2; ih++) {
                const float* row = h1p + (ic * 2 + ih) * 264;
                float hv[16];
                float4 q0 = *(const float4*)(row + w0);
                float4 q1 = *(const float4*)(row + w0 + 4);
                float4 q2 = *(const float4*)(row + w0 + 8);
                float4 q3 = *(const float4*)(row + w0 + 12);
                hv[0]=q0.x; hv[1]=q0.y; hv[2]=q0.z; hv[3]=q0.w;
                hv[4]=q1.x; hv[5]=q1.y; hv[6]=q1.z; hv[7]=q1.w;
                hv[8]=q2.x; hv[9]=q2.y; hv[10]=q2.z; hv[11]=q2.w;
                hv[12]=q3.x; hv[13]=q3.y; hv[14]=q3.z; hv[15]=q3.w;
#pragma unroll
                for (int m = 0; m < 11; m++) hp[ih][m] = pk(hv[2 + m], hv[3 + m]);
            }
            ull wp[2][2][5];
#pragma unroll
            for (int o = 0; o < 2; o++)
#pragma unroll
                for (int s = 0; s < 2; s++)
#pragma unroll
                    for (int kw = 0; kw < 5; kw++) {
                        float w = sw2[((oc0 + o) * 16 + ic) * 15 + (khA + s) * 5 + kw];
                        wp[o][s][kw] = pk(w, w);
                    }

            if (ph == 0) {
                combo<1, 0, 0>(accp, wp, hp);   // kh=2, rr=0, ih=0
                combo<0, 1, 0>(accp, wp, hp);   // kh=1, rr=1, ih=0
                combo<1, 1, 1>(accp, wp, hp);   // kh=2, rr=1, ih=1
            } else {
                combo<0, 0, 0>(accp, wp, hp);   // kh=0, rr=0, ih=0
                combo<1, 0, 1>(accp, wp, hp);   // kh=1, rr=0, ih=1
                combo<0, 1, 1>(accp, wp, hp);   // kh=0, rr=1, ih=1
            }
        }

#pragma unroll
        for (int o = 0; o < 2; o++) {
            int oc = oc0 + o;
            float bb = b2[oc];
            int fibase = oc * 256 + ph * 128 + pwg * 4;
            float4 fv4;
            float fvs[4];
#pragma unroll
            for (int jp = 0; jp < 4; jp++) {
                float v00, v01, v10, v11;
                upk(accp[o][0][jp], v00, v01);
                upk(accp[o][1][jp], v10, v11);
                v00 += bb; v01 += bb; v10 += bb; v11 += bb;
                v00 = (v00 >= 0.0f) ? v00 : 0.01f * v00;
                v01 = (v01 >= 0.0f) ? v01 : 0.01f * v01;
                v10 = (v10 >= 0.0f) ? v10 : 0.01f * v10;
                v11 = (v11 >= 0.0f) ? v11 : 0.01f * v11;
                float m = fmaxf(fmaxf(v00, v01), fmaxf(v10, v11));
                float fv = tanhf(m);
                fvs[jp] = fv;
                int fi = fibase + jp;
                a0 = fmaf(fv, __ldg(&Wout[2 * fi]), a0);
                a1 = fmaf(fv, __ldg(&Wout[2 * fi + 1]), a1);
            }
            fv4.x = fvs[0]; fv4.y = fvs[1]; fv4.z = fvs[2]; fv4.w = fvs[3];
            *(float4*)(dout + (size_t)FLAT_OFF + (size_t)b * 8192 + fibase) = fv4;
        }
    }

#pragma unroll
    for (int off = 16; off > 0; off >>= 1) {
        a0 += __shfl_down_sync(0xFFFFFFFFu, a0, off);
        a1 += __shfl_down_sync(0xFFFFFFFFu, a1, off);
    }
    if ((tid & 31) == 0) {
        bred[(tid >> 5) * 2 + 0] = a0;
        bred[(tid >> 5) * 2 + 1] = a1;
    }
    __syncthreads();
    if (tid == 0) {
        float s0 = bout[0], s1 = bout[1];
#pragma unroll
        for (int w = 0; w < 8; w++) { s0 += bred[2 * w]; s1 += bred[2 * w + 1]; }
        dout[(size_t)OUT_OFF + (size_t)b * 2 + 0] = s0;
        dout[(size_t)OUT_OFF + (size_t)b * 2 + 1] = s1;
    }
}

// ---------------- launcher ----------------
extern "C" void kernel_launch(void* const* d_in, const int* in_sizes, int n_in,
                              void* d_out, int out_size)
{
    const float* r_att  = (const float*)d_in[0];
    const float* p_att  = (const float*)d_in[1];
    const float* r_fun  = (const float*)d_in[2];
    const float* p_fun  = (const float*)d_in[3];
    const int*   idx    = (const int*)  d_in[4];
    const float* W_att1 = (const float*)d_in[5];
    const float* b_att1 = (const float*)d_in[6];
    const float* W_att2 = (const float*)d_in[7];
    const float* b_att2 = (const float*)d_in[8];
    const float* W_fun1 = (const float*)d_in[9];
    const float* b_fun1 = (const float*)d_in[10];
    const float* W_fun2 = (const float*)d_in[11];
    const float* b_fun2 = (const float*)d_in[12];
    const float* conv1w = (const float*)d_in[13];
    const float* conv1b = (const float*)d_in[14];
    const float* conv2w = (const float*)d_in[15];
    const float* conv2b = (const float*)d_in[16];
    const float* W_out  = (const float*)d_in[17];
    const float* b_out  = (const float*)d_in[18];
    float* out = (float*)d_out;

    float *h_att, *h_fun, *e, *part;
    cudaGetSymbolAddress((void**)&h_att, g_h_att);
    cudaGetSymbolAddress((void**)&h_fun, g_h_fun);
    cudaGetSymbolAddress((void**)&e,     g_e);
    cudaGetSymbolAddress((void**)&part,  g_part);

    const int smem128 = gemm_smem_bytes(128);   // 62208 B
    const int smem64  = gemm_smem_bytes(64);    // 43776 B
    cudaFuncSetAttribute(mma_gemm<128, 0, true>,
        cudaFuncAttributeMaxDynamicSharedMemorySize, smem128);
    cudaFuncSetAttribute(mma_gemm<128, 0, false>,
        cudaFuncAttributeMaxDynamicSharedMemorySize, smem128);

    const int epBlocks = (MROWS * 256 + 255) / 256;

    // G1: gelu(att @ W_att1 + b) -> h_att [3512 x 2048], K=3000 (aligned)
    mma_gemm<128, 0, true><<<dim3(2048 / 128, (MROWS + 127) / 128), 256, smem128>>>(
        r_att, p_att, N_R, MROWS, 2048, SIZE_R, SIZE_R,
        W_att1, b_att1, h_att, 2048, 0);

    // G2 split-K: h_att @ W_att2 partials -> part, then reduce+sigmoid
    mma_gemm<64, 2, true><<<dim3(2, (MROWS + 63) / 64, SPLITK), 256, smem64>>>(
        h_att, h_att, MROWS, MROWS, 256, 2048, 2048,
        W_att2, 0, part, 256, 512);
    splitk_epilogue<<<epBlocks, 256>>>(part, b_att2, e, out, 0);

    // G3: gelu(fun @ W_fun1 + b) -> h_fun [3512 x 4096], K=5603 (odd lda)
    mma_gemm<128, 0, false><<<dim3(4096 / 128, (MROWS + 127) / 128), 256, smem128>>>(
        r_fun, p_fun, N_R, MROWS, 4096, FUN_IN, FUN_IN,
        W_fun1, b_fun1, h_fun, 4096, 0);

    // G4 split-K: h_fun @ W_fun2 partials -> part, then reduce+sigmoid
    mma_gemm<64, 2, true><<<dim3(2, (MROWS + 63) / 64, SPLITK), 256, smem64>>>(
        h_fun, h_fun, MROWS, MROWS, 256, 4096, 4096,
        W_fun2, 0, part, 256, 1024);
    splitk_epilogue<<<epBlocks, 256>>>(part, b_fun2, e, out, 256);

    // pair head
    cudaFuncSetAttribute(pair_kernel,
        cudaFuncAttributeMaxDynamicSharedMemorySize, SM_TOTAL * 4);
    pair_kernel<<<NB, 256, SM_TOTAL * 4>>>(
        e, idx, conv1w, conv1b, conv2w, conv2b, W_out, b_out, out);
}

// round 11
// speedup vs baseline: 1.0416x; 1.0416x over previous
#include <cuda_runtime.h>
#include <math.h>
#include <stdint.h>

// ---------------- problem constants ----------------
#define N_R     2000
#define N_P     1512
#define MROWS   3512            // N_R + N_P
#define SIZE_R  3000
#define FUN_IN  5603
#define NB      8192            // batch of pairs
#define PROTEIN 1512

// d_out layout: e_r [2000,512] | e_p [1512,512] | output [8192,2] | flat [8192,8192]
#define E_P_OFF   1024000
#define OUT_OFF   1798144
#define FLAT_OFF  1814528

#define SPLITK 4

// smem strides (words)
#define ASTR 24     // As row stride: conflict-free 64-bit frag loads (12g+t perm mod 16)
#define BSTR 132    // Bs row stride: 132%32=4 -> rows {2t},{2t+1} conflict-free 32-bit loads

// ---------------- device scratch (no allocs allowed) ----------------
__device__ float g_h_att[MROWS * 2048];
__device__ float g_h_fun[MROWS * 4096];
__device__ float g_e[MROWS * 512];
__device__ float g_part[SPLITK * MROWS * 256];       // fun-chain partials
__device__ float g_part2[SPLITK * MROWS * 256];      // att-chain partials (separate: streams overlap)

// ---------------- helpers ----------------
typedef unsigned long long ull;

__device__ __forceinline__ void mma_tf32(float c[4],
    uint32_t a0, uint32_t a1, uint32_t a2, uint32_t a3,
    uint32_t b0, uint32_t b1)
{
    asm volatile(
        "mma.sync.aligned.m16n8k8.row.col.f32.tf32.tf32.f32 "
        "{%0,%1,%2,%3}, {%4,%5,%6,%7}, {%8,%9}, {%0,%1,%2,%3};\n"
        : "+f"(c[0]), "+f"(c[1]), "+f"(c[2]), "+f"(c[3])
        : "r"(a0), "r"(a1), "r"(a2), "r"(a3), "r"(b0), "r"(b1));
}

__device__ __forceinline__ void cp16(uint32_t dst, const void* src, int srcBytes) {
    asm volatile("cp.async.cg.shared.global [%0], [%1], 16, %2;\n"
                 :: "r"(dst), "l"(src), "r"(srcBytes));
}
__device__ __forceinline__ void cp4(uint32_t dst, const void* src, int srcBytes) {
    asm volatile("cp.async.ca.shared.global [%0], [%1], 4, %2;\n"
                 :: "r"(dst), "l"(src), "r"(srcBytes));
}
__device__ __forceinline__ void cp_commit() {
    asm volatile("cp.async.commit_group;\n" ::);
}
template<int W> __device__ __forceinline__ void cp_wait() {
    asm volatile("cp.async.wait_group %0;\n" :: "n"(W));
}

__device__ __forceinline__ ull pk(float lo, float hi) {
    ull r; asm("mov.b64 %0, {%1, %2};" : "=l"(r) : "f"(lo), "f"(hi)); return r;
}
__device__ __forceinline__ void upk(ull v, float& lo, float& hi) {
    asm("mov.b64 {%0, %1}, %2;" : "=f"(lo), "=f"(hi) : "l"(v));
}
__device__ __forceinline__ ull fma2(ull a, ull b, ull c) {
    ull d; asm("fma.rn.f32x2 %0, %1, %2, %3;" : "=l"(d) : "l"(a), "l"(b), "l"(c)); return d;
}

// ---------------- TF32 tensor-core GEMM, 3-stage cp.async pipeline ----------------
// Logical-k permutation: logical t <-> physical 2t, logical t+4 <-> physical 2t+1.
// MODE 0: gelu(exact) -> C[r*ldc + c], full K.
// MODE 2: raw partial -> C + blockIdx.z*M*256, K slice [z*ksl, min(K,(z+1)*ksl)).
template<int BM, int MODE, bool ALIGNED>
__global__ void __launch_bounds__(256, 2) mma_gemm(
    const float* __restrict__ A0, const float* __restrict__ A1, int split,
    int M, int N, int K, int lda,
    const float* __restrict__ B, const float* __restrict__ bias,
    float* __restrict__ C, int ldc, int ksl)
{
    constexpr int BN = 128;
    constexpr int BK = 16;
    constexpr int MT = BM / 32;
    constexpr int AF = (BM * BK) / (4 * 256);

    extern __shared__ uint32_t smemU[];
    uint32_t* As = smemU;                      // [3][BM][ASTR]
    uint32_t* Bs = smemU + 3 * BM * ASTR;      // [3][BK][BSTR]

    const int tid  = threadIdx.x;
    const int lane = tid & 31;
    const int warp = tid >> 5;
    const int wr = warp & 1;
    const int wc = warp >> 1;
    const int g = lane >> 2;
    const int t = lane & 3;

    const int rowBase = blockIdx.y * BM;
    const int colBase = blockIdx.x * BN;
    const int wm = wr * (BM / 2);
    const int wn = wc * 32;

    int kbeg = 0, kend = K;
    if (MODE == 2) { kbeg = blockIdx.z * ksl; kend = min(K, kbeg + ksl); }
    float* Cp = C;
    if (MODE == 2) Cp = C + (size_t)blockIdx.z * M * 256;

    float acc[MT][4][4];
#pragma unroll
    for (int i = 0; i < MT; i++)
#pragma unroll
        for (int j = 0; j < 4; j++)
#pragma unroll
            for (int q = 0; q < 4; q++) acc[i][j][q] = 0.0f;

    const float* Arow[AF];
#pragma unroll
    for (int i = 0; i < AF; i++) {
        int f = tid + i * 256;
        int m = f >> 2;
        int row = rowBase + m;
        Arow[i] = 0;
        if (row < M)
            Arow[i] = (row < split) ? (A0 + (size_t)row * lda)
                                    : (A1 + (size_t)(row - split) * lda);
    }

    const uint32_t AsAddr = (uint32_t)__cvta_generic_to_shared(As);
    const uint32_t BsAddr = (uint32_t)__cvta_generic_to_shared(Bs);

    const int nIter = (kend - kbeg + BK - 1) / BK;

    auto issueTile = [&](int it, int buf) {
        int k0 = kbeg + it * BK;
#pragma unroll
        for (int i = 0; i < AF; i++) {
            int f = tid + i * 256;
            int m = f >> 2;
            int kq = f & 3;
            int k = k0 + kq * 4;
            uint32_t dst = AsAddr + (uint32_t)((((buf * BM + m) * ASTR) + kq * 4) * 4);
            if (ALIGNED) {
                int bytes = 0;
                if (Arow[i]) { bytes = (kend - k) * 4; bytes = bytes < 0 ? 0 : (bytes > 16 ? 16 : bytes); }
                cp16(dst, Arow[i] ? (Arow[i] + k) : A0, bytes);
            } else {
#pragma unroll
                for (int j = 0; j < 4; j++) {
                    int bytes = (Arow[i] && (k + j) < kend) ? 4 : 0;
                    cp4(dst + 4 * j, Arow[i] ? (Arow[i] + k + j) : A0, bytes);
                }
            }
        }
#pragma unroll
        for (int i = 0; i < 2; i++) {
            int f = tid + i * 256;
            int kk = f >> 5;
            int nq = f & 31;
            int krow = k0 + kk;
            uint32_t dst = BsAddr + (uint32_t)((((buf * BK + kk) * BSTR) + nq * 4) * 4);
            int kc = krow < K - 1 ? krow : K - 1;
            const float* src = B + (size_t)kc * N + colBase + nq * 4;
            cp16(dst, src, krow < kend ? 16 : 0);
        }
        cp_commit();
    };

    issueTile(0, 0);
    if (nIter > 1) issueTile(1, 1);

    int buf = 0;
    for (int it = 0; it < nIter; it++) {
        if (it + 1 < nIter) cp_wait<1>(); else cp_wait<0>();
        __syncthreads();

#pragma unroll
        for (int ks = 0; ks < 2; ks++) {
            uint32_t afr[MT][4];
            uint32_t bfr[4][2];
#pragma unroll
            for (int mt = 0; mt < MT; mt++) {
                int r0 = wm + mt * 16 + g;
                const uint32_t* pa = As + (buf * BM + r0) * ASTR + ks * 8 + 2 * t;
                uint2 va = *(const uint2*)pa;
                uint2 vb = *(const uint2*)(pa + 8 * ASTR);
                afr[mt][0] = va.x;
                afr[mt][1] = vb.x;
                afr[mt][2] = va.y;
                afr[mt][3] = vb.y;
            }
#pragma unroll
            for (int nt = 0; nt < 4; nt++) {
                int c0 = wn + nt * 8 + g;
                const uint32_t* pb = Bs + (buf * BK + ks * 8 + 2 * t) * BSTR + c0;
                bfr[nt][0] = pb[0];
                bfr[nt][1] = pb[BSTR];
            }
#pragma unroll
            for (int mt = 0; mt < MT; mt++)
#pragma unroll
                for (int nt = 0; nt < 4; nt++)
                    mma_tf32(acc[mt][nt],
                             afr[mt][0], afr[mt][1], afr[mt][2], afr[mt][3],
                             bfr[nt][0], bfr[nt][1]);
        }
        __syncthreads();

        if (it + 2 < nIter) issueTile(it + 2, (it + 2) % 3);
        buf = (buf + 1 == 3) ? 0 : buf + 1;
    }

    // ---- epilogue ----
#pragma unroll
    for (int mt = 0; mt < MT; mt++) {
#pragma unroll
        for (int rh = 0; rh < 2; rh++) {
            int r = rowBase + wm + mt * 16 + g + rh * 8;
            if (r >= M) continue;
#pragma unroll
            for (int nt = 0; nt < 4; nt++) {
#pragma unroll
                for (int cj = 0; cj < 2; cj++) {
                    int c = colBase + wn + nt * 8 + 2 * t + cj;
                    if (c >= N) continue;
                    float v = acc[mt][nt][rh * 2 + cj];
                    if (MODE == 0) {
                        v += bias[c];
                        v = 0.5f * v * (1.0f + erff(v * 0.70710678118654752f));
                        C[(size_t)r * ldc + c] = v;
                    } else {
                        Cp[(size_t)r * 256 + c] = v;
                    }
                }
            }
        }
    }
}

// dynamic smem bytes for mma_gemm<BM,...>
static inline int gemm_smem_bytes(int BM) {
    return (3 * BM * ASTR + 3 * 16 * BSTR) * 4;
}

// ---------------- split-K reduce + bias + sigmoid + scatter ----------------
__global__ void __launch_bounds__(256) splitk_epilogue(
    const float* __restrict__ part, const float* __restrict__ bias,
    float* __restrict__ ebuf, float* __restrict__ dout, int ecol)
{
    int i = blockIdx.x * 256 + threadIdx.x;       // over MROWS*256
    int r = i >> 8;
    int c = i & 255;
    if (r >= MROWS) return;
    float v = part[i];
#pragma unroll
    for (int s = 1; s < SPLITK; s++) v += part[i + (size_t)s * MROWS * 256];
    v = 1.0f / (1.0f + expf(-(v + bias[c])));
    ebuf[(size_t)r * 512 + ecol + c] = v;
    if (r < N_R)
        dout[(size_t)r * 512 + ecol + c] = v;
    else
        dout[(size_t)E_P_OFF + (size_t)(r - N_R) * 512 + ecol + c] = v;
}

// ---------------- pair kernel ----------------
#define SM_XP    0
#define SM_H1P   3120
#define SM_SW2   (3120 + 8448)
#define SM_SW1   (3120 + 8448 + 7680)
#define SM_BRED  (3120 + 8448 + 7680 + 240)
#define SM_TOTAL (3120 + 8448 + 7680 + 240 + 16)

template<int S, int RR, int IH>
__device__ __forceinline__ void combo(
    ull accp[2][2][4], const ull wp[2][2][5], const ull hp[2][11])
{
#pragma unroll
    for (int jp = 0; jp < 4; jp++)
#pragma unroll
        for (int kw = 0; kw < 5; kw++) {
            accp[0][RR][jp] = fma2(wp[0][S][kw], hp[IH][2 * jp + kw], accp[0][RR][jp]);
            accp[1][RR][jp] = fma2(wp[1][S][kw], hp[IH][2 * jp + kw], accp[1][RR][jp]);
        }
}

__global__ void __launch_bounds__(256) pair_kernel(
    const float* __restrict__ e, const int* __restrict__ idx,
    const float* __restrict__ w1, const float* __restrict__ b1,
    const float* __restrict__ w2, const float* __restrict__ b2,
    const float* __restrict__ Wout, const float* __restrict__ bout,
    float* __restrict__ dout)
{
    extern __shared__ float sm[];
    float* xp   = sm + SM_XP;    // [6][520]
    float* h1p  = sm + SM_H1P;   // [16][2][264]
    float* sw2  = sm + SM_SW2;   // [32][16][15]
    float* sw1  = sm + SM_SW1;   // [16][15]
    float* bred = sm + SM_BRED;  // [16]

    const int tid = threadIdx.x;
    const int b = blockIdx.x;

    const int iv = idx[b];
    const int rno = iv / PROTEIN;
    const int pno = iv % PROTEIN;
    const float* er = e + (size_t)rno * 512;
    const float* ep = e + (size_t)(N_R + pno) * 512;

    for (int i = tid; i < 6 * 520; i += 256) xp[i] = 0.0f;
    for (int i = tid; i < 16 * 2 * 264; i += 256) h1p[i] = 0.0f;
    for (int i = tid; i < 240; i += 256) sw1[i] = w1[i];
    for (int i = tid; i < 7680; i += 256) sw2[i] = w2[i];
    for (int w = tid; w < 512; w += 256) {
        xp[2 * 520 + 4 + w] = er[w];
        xp[3 * 520 + 4 + w] = ep[w];
    }
    __syncthreads();

    // conv1 + leaky + avgpool
    for (int id = tid; id < 16 * 2 * 256; id += 256) {
        int c  = id >> 9;
        int rm = id & 511;
        int ph = rm >> 8;
        int pw = rm & 255;
        float wv[15];
#pragma unroll
        for (int q = 0; q < 15; q++) wv[q] = sw1[c * 15 + q];
        float bb = b1[c];
        float sum = 0.0f;
#pragma unroll
        for (int oh2 = 0; oh2 < 2; oh2++) {
#pragma unroll
            for (int ow2 = 0; ow2 < 2; ow2++) {
                int oh = 2 * ph + oh2;
                int ow = 2 * pw + ow2;
                float v = bb;
#pragma unroll
                for (int kh = 0; kh < 3; kh++) {
                    const float* xr = xp + (oh + kh) * 520 + (ow + 2);
#pragma unroll
                    for (int kw = 0; kw < 5; kw++)
                        v = fmaf(wv[kh * 5 + kw], xr[kw], v);
                }
                sum += (v >= 0.0f) ? v : 0.01f * v;
            }
        }
        h1p[(c * 2 + ph) * 264 + 4 + pw] = 0.25f * sum;
    }
    __syncthreads();

    // conv2 (f32x2 packed) + leaky + maxpool + tanh + flat + W_out dot
    float a0 = 0.0f, a1 = 0.0f;

    for (int tt = 0; tt < 4; tt++) {
        int task = tt * 256 + tid;
        int ocp = task >> 6;
        int ph  = (task >> 5) & 1;
        int pwg = task & 31;
        int oc0 = ocp * 2;
        int w0 = pwg * 8;

        ull accp[2][2][4];
#pragma unroll
        for (int o = 0; o < 2; o++)
#pragma unroll
            for (int r = 0; r < 2; r++)
#pragma unroll
                for (int jp = 0; jp < 4; jp++) accp[o][r][jp] = 0ull;

        const int khA = ph ? 0 : 1;   // needed kh rows: {khA, khA+1}

        for (int ic = 0; ic < 16; ic++) {
            ull hp[2][11];
#pragma unroll
            for (int ih = 0; ih < 2; ih++) {
                const float* row = h1p + (ic * 2 + ih) * 264;
                float hv[16];
                float4 q0 = *(const float4*)(row + w0);
                float4 q1 = *(const float4*)(row + w0 + 4);
                float4 q2 = *(const float4*)(row + w0 + 8);
                float4 q3 = *(const float4*)(row + w0 + 12);
                hv[0]=q0.x; hv[1]=q0.y; hv[2]=q0.z; hv[3]=q0.w;
                hv[4]=q1.x; hv[5]=q1.y; hv[6]=q1.z; hv[7]=q1.w;
                hv[8]=q2.x; hv[9]=q2.y; hv[10]=q2.z; hv[11]=q2.w;
                hv[12]=q3.x; hv[13]=q3.y; hv[14]=q3.z; hv[15]=q3.w;
#pragma unroll
                for (int m = 0; m < 11; m++) hp[ih][m] = pk(hv[2 + m], hv[3 + m]);
            }
            ull wp[2][2][5];
#pragma unroll
            for (int o = 0; o < 2; o++)
#pragma unroll
                for (int s = 0; s < 2; s++)
#pragma unroll
                    for (int kw = 0; kw < 5; kw++) {
                        float w = sw2[((oc0 + o) * 16 + ic) * 15 + (khA + s) * 5 + kw];
                        wp[o][s][kw] = pk(w, w);
                    }

            if (ph == 0) {
                combo<1, 0, 0>(accp, wp, hp);   // kh=2, rr=0, ih=0
                combo<0, 1, 0>(accp, wp, hp);   // kh=1, rr=1, ih=0
                combo<1, 1, 1>(accp, wp, hp);   // kh=2, rr=1, ih=1
            } else {
                combo<0, 0, 0>(accp, wp, hp);   // kh=0, rr=0, ih=0
                combo<1, 0, 1>(accp, wp, hp);   // kh=1, rr=0, ih=1
                combo<0, 1, 1>(accp, wp, hp);   // kh=0, rr=1, ih=1
            }
        }

#pragma unroll
        for (int o = 0; o < 2; o++) {
            int oc = oc0 + o;
            float bb = b2[oc];
            int fibase = oc * 256 + ph * 128 + pwg * 4;
            float4 fv4;
            float fvs[4];
#pragma unroll
            for (int jp = 0; jp < 4; jp++) {
                float v00, v01, v10, v11;
                upk(accp[o][0][jp], v00, v01);
                upk(accp[o][1][jp], v10, v11);
                v00 += bb; v01 += bb; v10 += bb; v11 += bb;
                v00 = (v00 >= 0.0f) ? v00 : 0.01f * v00;
                v01 = (v01 >= 0.0f) ? v01 : 0.01f * v01;
                v10 = (v10 >= 0.0f) ? v10 : 0.01f * v10;
                v11 = (v11 >= 0.0f) ? v11 : 0.01f * v11;
                float m = fmaxf(fmaxf(v00, v01), fmaxf(v10, v11));
                float fv = tanhf(m);
                fvs[jp] = fv;
                int fi = fibase + jp;
                a0 = fmaf(fv, __ldg(&Wout[2 * fi]), a0);
                a1 = fmaf(fv, __ldg(&Wout[2 * fi + 1]), a1);
            }
            fv4.x = fvs[0]; fv4.y = fvs[1]; fv4.z = fvs[2]; fv4.w = fvs[3];
            *(float4*)(dout + (size_t)FLAT_OFF + (size_t)b * 8192 + fibase) = fv4;
        }
    }

#pragma unroll
    for (int off = 16; off > 0; off >>= 1) {
        a0 += __shfl_down_sync(0xFFFFFFFFu, a0, off);
        a1 += __shfl_down_sync(0xFFFFFFFFu, a1, off);
    }
    if ((tid & 31) == 0) {
        bred[(tid >> 5) * 2 + 0] = a0;
        bred[(tid >> 5) * 2 + 1] = a1;
    }
    __syncthreads();
    if (tid == 0) {
        float s0 = bout[0], s1 = bout[1];
#pragma unroll
        for (int w = 0; w < 8; w++) { s0 += bred[2 * w]; s1 += bred[2 * w + 1]; }
        dout[(size_t)OUT_OFF + (size_t)b * 2 + 0] = s0;
        dout[(size_t)OUT_OFF + (size_t)b * 2 + 1] = s1;
    }
}

// ---------------- launcher ----------------
extern "C" void kernel_launch(void* const* d_in, const int* in_sizes, int n_in,
                              void* d_out, int out_size)
{
    const float* r_att  = (const float*)d_in[0];
    const float* p_att  = (const float*)d_in[1];
    const float* r_fun  = (const float*)d_in[2];
    const float* p_fun  = (const float*)d_in[3];
    const int*   idx    = (const int*)  d_in[4];
    const float* W_att1 = (const float*)d_in[5];
    const float* b_att1 = (const float*)d_in[6];
    const float* W_att2 = (const float*)d_in[7];
    const float* b_att2 = (const float*)d_in[8];
    const float* W_fun1 = (const float*)d_in[9];
    const float* b_fun1 = (const float*)d_in[10];
    const float* W_fun2 = (const float*)d_in[11];
    const float* b_fun2 = (const float*)d_in[12];
    const float* conv1w = (const float*)d_in[13];
    const float* conv1b = (const float*)d_in[14];
    const float* conv2w = (const float*)d_in[15];
    const float* conv2b = (const float*)d_in[16];
    const float* W_out  = (const float*)d_in[17];
    const float* b_out  = (const float*)d_in[18];
    float* out = (float*)d_out;

    float *h_att, *h_fun, *e, *part, *part2;
    cudaGetSymbolAddress((void**)&h_att, g_h_att);
    cudaGetSymbolAddress((void**)&h_fun, g_h_fun);
    cudaGetSymbolAddress((void**)&e,     g_e);
    cudaGetSymbolAddress((void**)&part,  g_part);
    cudaGetSymbolAddress((void**)&part2, g_part2);

    // persistent side streams + events (host infra; created once, reused; the
    // captured graph gets the fork/join structure via the event edges below)
    static cudaStream_t sA = 0, sF = 0;
    static cudaEvent_t evFork = 0, evA = 0, evF = 0;
    if (!sA) {
        cudaStreamCreateWithFlags(&sA, cudaStreamNonBlocking);
        cudaStreamCreateWithFlags(&sF, cudaStreamNonBlocking);
        cudaEventCreateWithFlags(&evFork, cudaEventDisableTiming);
        cudaEventCreateWithFlags(&evA,    cudaEventDisableTiming);
        cudaEventCreateWithFlags(&evF,    cudaEventDisableTiming);
    }

    const int smem128 = gemm_smem_bytes(128);   // 62208 B
    const int smem64  = gemm_smem_bytes(64);    // 43776 B
    static bool attrSet = false;
    if (!attrSet) {
        cudaFuncSetAttribute(mma_gemm<128, 0, true>,
            cudaFuncAttributeMaxDynamicSharedMemorySize, smem128);
        cudaFuncSetAttribute(mma_gemm<128, 0, false>,
            cudaFuncAttributeMaxDynamicSharedMemorySize, smem128);
        cudaFuncSetAttribute(pair_kernel,
            cudaFuncAttributeMaxDynamicSharedMemorySize, SM_TOTAL * 4);
        attrSet = true;
    }

    const int epBlocks = (MROWS * 256 + 255) / 256;

    // ---- fork from the (captured) default stream ----
    cudaEventRecord(evFork, 0);
    cudaStreamWaitEvent(sA, evFork, 0);
    cudaStreamWaitEvent(sF, evFork, 0);

    // ===== att chain on sA =====
    mma_gemm<128, 0, true><<<dim3(2048 / 128, (MROWS + 127) / 128), 256, smem128, sA>>>(
        r_att, p_att, N_R, MROWS, 2048, SIZE_R, SIZE_R,
        W_att1, b_att1, h_att, 2048, 0);
    mma_gemm<64, 2, true><<<dim3(2, (MROWS + 63) / 64, SPLITK), 256, smem64, sA>>>(
        h_att, h_att, MROWS, MROWS, 256, 2048, 2048,
        W_att2, 0, part2, 256, 512);
    splitk_epilogue<<<epBlocks, 256, 0, sA>>>(part2, b_att2, e, out, 0);
    cudaEventRecord(evA, sA);

    // ===== fun chain on sF =====
    mma_gemm<128, 0, false><<<dim3(4096 / 128, (MROWS + 127) / 128), 256, smem128, sF>>>(
        r_fun, p_fun, N_R, MROWS, 4096, FUN_IN, FUN_IN,
        W_fun1, b_fun1, h_fun, 4096, 0);
    mma_gemm<64, 2, true><<<dim3(2, (MROWS + 63) / 64, SPLITK), 256, smem64, sF>>>(
        h_fun, h_fun, MROWS, MROWS, 256, 4096, 4096,
        W_fun2, 0, part, 256, 1024);
    splitk_epilogue<<<epBlocks, 256, 0, sF>>>(part, b_fun2, e, out, 256);
    cudaEventRecord(evF, sF);

    // ---- join back to default stream ----
    cudaStreamWaitEvent(0, evA, 0);
    cudaStreamWaitEvent(0, evF, 0);

    // pair head (needs both halves of e)
    pair_kernel<<<NB, 256, SM_TOTAL * 4>>>(
        e, idx, conv1w, conv1b, conv2w, conv2b, W_out, b_out, out);
}

// round 12
// speedup vs baseline: 1.1479x; 1.1021x over previous
#include <cuda_runtime.h>
#include <math.h>
#include <stdint.h>

// ---------------- problem constants ----------------
#define N_R     2000
#define N_P     1512
#define MROWS   3512            // N_R + N_P
#define SIZE_R  3000
#define FUN_IN  5603
#define FUN_PAD 5632            // padded row stride (16B-aligned rows)
#define NB      8192            // batch of pairs
#define PROTEIN 1512

// d_out layout: e_r [2000,512] | e_p [1512,512] | output [8192,2] | flat [8192,8192]
#define E_P_OFF   1024000
#define OUT_OFF   1798144
#define FLAT_OFF  1814528

#define SPLITK 4

// smem strides (words)
#define ASTR 24     // As row stride: conflict-free 64-bit frag loads
#define BSTR 132    // Bs row stride: conflict-free 32-bit frag loads

// ---------------- device scratch (no allocs allowed) ----------------
__device__ float g_h_att[MROWS * 2048];
__device__ float g_h_fun[MROWS * 4096];
__device__ float g_e[MROWS * 512];
__device__ float g_part[SPLITK * MROWS * 256];       // fun-chain partials
__device__ float g_part2[SPLITK * MROWS * 256];      // att-chain partials
__device__ float g_fun_pack[MROWS * FUN_PAD];        // aligned repack of [r_fun; p_fun]

// ---------------- helpers ----------------
typedef unsigned long long ull;

__device__ __forceinline__ void mma_tf32(float c[4],
    uint32_t a0, uint32_t a1, uint32_t a2, uint32_t a3,
    uint32_t b0, uint32_t b1)
{
    asm volatile(
        "mma.sync.aligned.m16n8k8.row.col.f32.tf32.tf32.f32 "
        "{%0,%1,%2,%3}, {%4,%5,%6,%7}, {%8,%9}, {%0,%1,%2,%3};\n"
        : "+f"(c[0]), "+f"(c[1]), "+f"(c[2]), "+f"(c[3])
        : "r"(a0), "r"(a1), "r"(a2), "r"(a3), "r"(b0), "r"(b1));
}

__device__ __forceinline__ void cp16(uint32_t dst, const void* src, int srcBytes) {
    asm volatile("cp.async.cg.shared.global [%0], [%1], 16, %2;\n"
                 :: "r"(dst), "l"(src), "r"(srcBytes));
}
__device__ __forceinline__ void cp_commit() {
    asm volatile("cp.async.commit_group;\n" ::);
}
template<int W> __device__ __forceinline__ void cp_wait() {
    asm volatile("cp.async.wait_group %0;\n" :: "n"(W));
}

__device__ __forceinline__ ull pk(float lo, float hi) {
    ull r; asm("mov.b64 %0, {%1, %2};" : "=l"(r) : "f"(lo), "f"(hi)); return r;
}
__device__ __forceinline__ void upk(ull v, float& lo, float& hi) {
    asm("mov.b64 {%0, %1}, %2;" : "=f"(lo), "=f"(hi) : "l"(v));
}
__device__ __forceinline__ ull fma2(ull a, ull b, ull c) {
    ull d; asm("fma.rn.f32x2 %0, %1, %2, %3;" : "=l"(d) : "l"(a), "l"(b), "l"(c)); return d;
}

// ---------------- repack [r_fun; p_fun] -> g_fun_pack (stride FUN_PAD) ----------------
__global__ void __launch_bounds__(256) repack_fun(
    const float* __restrict__ r_fun, const float* __restrict__ p_fun,
    float* __restrict__ dst)
{
    int row = blockIdx.y;
    int c = blockIdx.x * 256 + threadIdx.x;
    if (c >= FUN_IN) return;
    const float* src = (row < N_R) ? (r_fun + (size_t)row * FUN_IN)
                                   : (p_fun + (size_t)(row - N_R) * FUN_IN);
    dst[(size_t)row * FUN_PAD + c] = src[c];
}

// ---------------- TF32 tensor-core GEMM, 3-stage cp.async pipeline ----------------
// Logical-k permutation: logical t <-> physical 2t, logical t+4 <-> physical 2t+1.
// MODE 0: gelu(exact) -> C[r*ldc + c], full K.
// MODE 2: raw partial -> C + blockIdx.z*M*256, K slice [z*ksl, min(K,(z+1)*ksl)).
// Requires: lda*4 and K-tile offsets 16B-aligned (all call sites now satisfy this).
template<int BM, int MODE>
__global__ void __launch_bounds__(256, 2) mma_gemm(
    const float* __restrict__ A0, const float* __restrict__ A1, int split,
    int M, int N, int K, int lda,
    const float* __restrict__ B, const float* __restrict__ bias,
    float* __restrict__ C, int ldc, int ksl)
{
    constexpr int BN = 128;
    constexpr int BK = 16;
    constexpr int MT = BM / 32;
    constexpr int AF = (BM * BK) / (4 * 256);

    extern __shared__ uint32_t smemU[];
    uint32_t* As = smemU;                      // [3][BM][ASTR]
    uint32_t* Bs = smemU + 3 * BM * ASTR;      // [3][BK][BSTR]

    const int tid  = threadIdx.x;
    const int lane = tid & 31;
    const int warp = tid >> 5;
    const int wr = warp & 1;
    const int wc = warp >> 1;
    const int g = lane >> 2;
    const int t = lane & 3;

    const int rowBase = blockIdx.y * BM;
    const int colBase = blockIdx.x * BN;
    const int wm = wr * (BM / 2);
    const int wn = wc * 32;

    int kbeg = 0, kend = K;
    if (MODE == 2) { kbeg = blockIdx.z * ksl; kend = min(K, kbeg + ksl); }
    float* Cp = C;
    if (MODE == 2) Cp = C + (size_t)blockIdx.z * M * 256;

    float acc[MT][4][4];
#pragma unroll
    for (int i = 0; i < MT; i++)
#pragma unroll
        for (int j = 0; j < 4; j++)
#pragma unroll
            for (int q = 0; q < 4; q++) acc[i][j][q] = 0.0f;

    const float* Arow[AF];
#pragma unroll
    for (int i = 0; i < AF; i++) {
        int f = tid + i * 256;
        int m = f >> 2;
        int row = rowBase + m;
        Arow[i] = 0;
        if (row < M)
            Arow[i] = (row < split) ? (A0 + (size_t)row * lda)
                                    : (A1 + (size_t)(row - split) * lda);
    }

    const uint32_t AsAddr = (uint32_t)__cvta_generic_to_shared(As);
    const uint32_t BsAddr = (uint32_t)__cvta_generic_to_shared(Bs);

    const int nIter = (kend - kbeg + BK - 1) / BK;

    auto issueTile = [&](int it, int buf) {
        int k0 = kbeg + it * BK;
#pragma unroll
        for (int i = 0; i < AF; i++) {
            int f = tid + i * 256;
            int m = f >> 2;
            int kq = f & 3;
            int k = k0 + kq * 4;
            uint32_t dst = AsAddr + (uint32_t)((((buf * BM + m) * ASTR) + kq * 4) * 4);
            int bytes = 0;
            if (Arow[i]) { bytes = (kend - k) * 4; bytes = bytes < 0 ? 0 : (bytes > 16 ? 16 : bytes); }
            cp16(dst, Arow[i] ? (Arow[i] + k) : A0, bytes);
        }
#pragma unroll
        for (int i = 0; i < 2; i++) {
            int f = tid + i * 256;
            int kk = f >> 5;
            int nq = f & 31;
            int krow = k0 + kk;
            uint32_t dst = BsAddr + (uint32_t)((((buf * BK + kk) * BSTR) + nq * 4) * 4);
            int kc = krow < K - 1 ? krow : K - 1;
            const float* src = B + (size_t)kc * N + colBase + nq * 4;
            cp16(dst, src, krow < kend ? 16 : 0);
        }
        cp_commit();
    };

    issueTile(0, 0);
    if (nIter > 1) issueTile(1, 1);

    int buf = 0;
    for (int it = 0; it < nIter; it++) {
        if (it + 1 < nIter) cp_wait<1>(); else cp_wait<0>();
        __syncthreads();

#pragma unroll
        for (int ks = 0; ks < 2; ks++) {
            uint32_t afr[MT][4];
            uint32_t bfr[4][2];
#pragma unroll
            for (int mt = 0; mt < MT; mt++) {
                int r0 = wm + mt * 16 + g;
                const uint32_t* pa = As + (buf * BM + r0) * ASTR + ks * 8 + 2 * t;
                uint2 va = *(const uint2*)pa;
                uint2 vb = *(const uint2*)(pa + 8 * ASTR);
                afr[mt][0] = va.x;
                afr[mt][1] = vb.x;
                afr[mt][2] = va.y;
                afr[mt][3] = vb.y;
            }
#pragma unroll
            for (int nt = 0; nt < 4; nt++) {
                int c0 = wn + nt * 8 + g;
                const uint32_t* pb = Bs + (buf * BK + ks * 8 + 2 * t) * BSTR + c0;
                bfr[nt][0] = pb[0];
                bfr[nt][1] = pb[BSTR];
            }
#pragma unroll
            for (int mt = 0; mt < MT; mt++)
#pragma unroll
                for (int nt = 0; nt < 4; nt++)
                    mma_tf32(acc[mt][nt],
                             afr[mt][0], afr[mt][1], afr[mt][2], afr[mt][3],
                             bfr[nt][0], bfr[nt][1]);
        }
        __syncthreads();

        if (it + 2 < nIter) issueTile(it + 2, (it + 2) % 3);
        buf = (buf + 1 == 3) ? 0 : buf + 1;
    }

    // ---- epilogue ----
#pragma unroll
    for (int mt = 0; mt < MT; mt++) {
#pragma unroll
        for (int rh = 0; rh < 2; rh++) {
            int r = rowBase + wm + mt * 16 + g + rh * 8;
            if (r >= M) continue;
#pragma unroll
            for (int nt = 0; nt < 4; nt++) {
#pragma unroll
                for (int cj = 0; cj < 2; cj++) {
                    int c = colBase + wn + nt * 8 + 2 * t + cj;
                    if (c >= N) continue;
                    float v = acc[mt][nt][rh * 2 + cj];
                    if (MODE == 0) {
                        v += bias[c];
                        v = 0.5f * v * (1.0f + erff(v * 0.70710678118654752f));
                        C[(size_t)r * ldc + c] = v;
                    } else {
                        Cp[(size_t)r * 256 + c] = v;
                    }
                }
            }
        }
    }
}

// dynamic smem bytes for mma_gemm<BM,...>
static inline int gemm_smem_bytes(int BM) {
    return (3 * BM * ASTR + 3 * 16 * BSTR) * 4;
}

// ---------------- split-K reduce + bias + sigmoid + scatter ----------------
__global__ void __launch_bounds__(256) splitk_epilogue(
    const float* __restrict__ part, const float* __restrict__ bias,
    float* __restrict__ ebuf, float* __restrict__ dout, int ecol)
{
    int i = blockIdx.x * 256 + threadIdx.x;       // over MROWS*256
    int r = i >> 8;
    int c = i & 255;
    if (r >= MROWS) return;
    float v = part[i];
#pragma unroll
    for (int s = 1; s < SPLITK; s++) v += part[i + (size_t)s * MROWS * 256];
    v = 1.0f / (1.0f + expf(-(v + bias[c])));
    ebuf[(size_t)r * 512 + ecol + c] = v;
    if (r < N_R)
        dout[(size_t)r * 512 + ecol + c] = v;
    else
        dout[(size_t)E_P_OFF + (size_t)(r - N_R) * 512 + ecol + c] = v;
}

// ---------------- pair kernel ----------------
#define SM_XP    0
#define SM_H1P   3120
#define SM_SW2   (3120 + 8448)
#define SM_SW1   (3120 + 8448 + 7680)
#define SM_BRED  (3120 + 8448 + 7680 + 240)
#define SM_TOTAL (3120 + 8448 + 7680 + 240 + 16)

template<int S, int RR, int IH>
__device__ __forceinline__ void combo(
    ull accp[2][2][4], const ull wp[2][2][5], const ull hp[2][11])
{
#pragma unroll
    for (int jp = 0; jp < 4; jp++)
#pragma unroll
        for (int kw = 0; kw < 5; kw++) {
            accp[0][RR][jp] = fma2(wp[0][S][kw], hp[IH][2 * jp + kw], accp[0][RR][jp]);
            accp[1][RR][jp] = fma2(wp[1][S][kw], hp[IH][2 * jp + kw], accp[1][RR][jp]);
        }
}

__global__ void __launch_bounds__(256) pair_kernel(
    const float* __restrict__ e, const int* __restrict__ idx,
    const float* __restrict__ w1, const float* __restrict__ b1,
    const float* __restrict__ w2, const float* __restrict__ b2,
    const float* __restrict__ Wout, const float* __restrict__ bout,
    float* __restrict__ dout)
{
    extern __shared__ float sm[];
    float* xp   = sm + SM_XP;    // [6][520]
    float* h1p  = sm + SM_H1P;   // [16][2][264]
    float* sw2  = sm + SM_SW2;   // [32][16][15]
    float* sw1  = sm + SM_SW1;   // [16][15]
    float* bred = sm + SM_BRED;  // [16]

    const int tid = threadIdx.x;
    const int b = blockIdx.x;

    const int iv = idx[b];
    const int rno = iv / PROTEIN;
    const int pno = iv % PROTEIN;
    const float* er = e + (size_t)rno * 512;
    const float* ep = e + (size_t)(N_R + pno) * 512;

    for (int i = tid; i < 6 * 520; i += 256) xp[i] = 0.0f;
    for (int i = tid; i < 16 * 2 * 264; i += 256) h1p[i] = 0.0f;
    for (int i = tid; i < 240; i += 256) sw1[i] = w1[i];
    for (int i = tid; i < 7680; i += 256) sw2[i] = w2[i];
    for (int w = tid; w < 512; w += 256) {
        xp[2 * 520 + 4 + w] = er[w];
        xp[3 * 520 + 4 + w] = ep[w];
    }
    __syncthreads();

    // conv1 + leaky + avgpool
    for (int id = tid; id < 16 * 2 * 256; id += 256) {
        int c  = id >> 9;
        int rm = id & 511;
        int ph = rm >> 8;
        int pw = rm & 255;
        float wv[15];
#pragma unroll
        for (int q = 0; q < 15; q++) wv[q] = sw1[c * 15 + q];
        float bb = b1[c];
        float sum = 0.0f;
#pragma unroll
        for (int oh2 = 0; oh2 < 2; oh2++) {
#pragma unroll
            for (int ow2 = 0; ow2 < 2; ow2++) {
                int oh = 2 * ph + oh2;
                int ow = 2 * pw + ow2;
                float v = bb;
#pragma unroll
                for (int kh = 0; kh < 3; kh++) {
                    const float* xr = xp + (oh + kh) * 520 + (ow + 2);
#pragma unroll
                    for (int kw = 0; kw < 5; kw++)
                        v = fmaf(wv[kh * 5 + kw], xr[kw], v);
                }
                sum += (v >= 0.0f) ? v : 0.01f * v;
            }
        }
        h1p[(c * 2 + ph) * 264 + 4 + pw] = 0.25f * sum;
    }
    __syncthreads();

    // conv2 (f32x2 packed) + leaky + maxpool + tanh + flat + W_out dot
    float a0 = 0.0f, a1 = 0.0f;

    for (int tt = 0; tt < 4; tt++) {
        int task = tt * 256 + tid;
        int ocp = task >> 6;
        int ph  = (task >> 5) & 1;
        int pwg = task & 31;
        int oc0 = ocp * 2;
        int w0 = pwg * 8;

        ull accp[2][2][4];
#pragma unroll
        for (int o = 0; o < 2; o++)
#pragma unroll
            for (int r = 0; r < 2; r++)
#pragma unroll
                for (int jp = 0; jp < 4; jp++) accp[o][r][jp] = 0ull;

        const int khA = ph ? 0 : 1;   // needed kh rows: {khA, khA+1}

        for (int ic = 0; ic < 16; ic++) {
            ull hp[2][11];
#pragma unroll
            for (int ih = 0; ih < 2; ih++) {
                const float* row = h1p + (ic * 2 + ih) * 264;
                float hv[16];
                float4 q0 = *(const float4*)(row + w0);
                float4 q1 = *(const float4*)(row + w0 + 4);
                float4 q2 = *(const float4*)(row + w0 + 8);
                float4 q3 = *(const float4*)(row + w0 + 12);
                hv[0]=q0.x; hv[1]=q0.y; hv[2]=q0.z; hv[3]=q0.w;
                hv[4]=q1.x; hv[5]=q1.y; hv[6]=q1.z; hv[7]=q1.w;
                hv[8]=q2.x; hv[9]=q2.y; hv[10]=q2.z; hv[11]=q2.w;
                hv[12]=q3.x; hv[13]=q3.y; hv[14]=q3.z; hv[15]=q3.w;
#pragma unroll
                for (int m = 0; m < 11; m++) hp[ih][m] = pk(hv[2 + m], hv[3 + m]);
            }
            ull wp[2][2][5];
#pragma unroll
            for (int o = 0; o < 2; o++)
#pragma unroll
                for (int s = 0; s < 2; s++)
#pragma unroll
                    for (int kw = 0; kw < 5; kw++) {
                        float w = sw2[((oc0 + o) * 16 + ic) * 15 + (khA + s) * 5 + kw];
                        wp[o][s][kw] = pk(w, w);
                    }

            if (ph == 0) {
                combo<1, 0, 0>(accp, wp, hp);   // kh=2, rr=0, ih=0
                combo<0, 1, 0>(accp, wp, hp);   // kh=1, rr=1, ih=0
                combo<1, 1, 1>(accp, wp, hp);   // kh=2, rr=1, ih=1
            } else {
                combo<0, 0, 0>(accp, wp, hp);   // kh=0, rr=0, ih=0
                combo<1, 0, 1>(accp, wp, hp);   // kh=1, rr=0, ih=1
                combo<0, 1, 1>(accp, wp, hp);   // kh=0, rr=1, ih=1
            }
        }

#pragma unroll
        for (int o = 0; o < 2; o++) {
            int oc = oc0 + o;
            float bb = b2[oc];
            int fibase = oc * 256 + ph * 128 + pwg * 4;
            float4 fv4;
            float fvs[4];
#pragma unroll
            for (int jp = 0; jp < 4; jp++) {
                float v00, v01, v10, v11;
                upk(accp[o][0][jp], v00, v01);
                upk(accp[o][1][jp], v10, v11);
                v00 += bb; v01 += bb; v10 += bb; v11 += bb;
                v00 = (v00 >= 0.0f) ? v00 : 0.01f * v00;
                v01 = (v01 >= 0.0f) ? v01 : 0.01f * v01;
                v10 = (v10 >= 0.0f) ? v10 : 0.01f * v10;
                v11 = (v11 >= 0.0f) ? v11 : 0.01f * v11;
                float m = fmaxf(fmaxf(v00, v01), fmaxf(v10, v11));
                float fv = tanhf(m);
                fvs[jp] = fv;
                int fi = fibase + jp;
                a0 = fmaf(fv, __ldg(&Wout[2 * fi]), a0);
                a1 = fmaf(fv, __ldg(&Wout[2 * fi + 1]), a1);
            }
            fv4.x = fvs[0]; fv4.y = fvs[1]; fv4.z = fvs[2]; fv4.w = fvs[3];
            *(float4*)(dout + (size_t)FLAT_OFF + (size_t)b * 8192 + fibase) = fv4;
        }
    }

#pragma unroll
    for (int off = 16; off > 0; off >>= 1) {
        a0 += __shfl_down_sync(0xFFFFFFFFu, a0, off);
        a1 += __shfl_down_sync(0xFFFFFFFFu, a1, off);
    }
    if ((tid & 31) == 0) {
        bred[(tid >> 5) * 2 + 0] = a0;
        bred[(tid >> 5) * 2 + 1] = a1;
    }
    __syncthreads();
    if (tid == 0) {
        float s0 = bout[0], s1 = bout[1];
#pragma unroll
        for (int w = 0; w < 8; w++) { s0 += bred[2 * w]; s1 += bred[2 * w + 1]; }
        dout[(size_t)OUT_OFF + (size_t)b * 2 + 0] = s0;
        dout[(size_t)OUT_OFF + (size_t)b * 2 + 1] = s1;
    }
}

// ---------------- launcher ----------------
extern "C" void kernel_launch(void* const* d_in, const int* in_sizes, int n_in,
                              void* d_out, int out_size)
{
    const float* r_att  = (const float*)d_in[0];
    const float* p_att  = (const float*)d_in[1];
    const float* r_fun  = (const float*)d_in[2];
    const float* p_fun  = (const float*)d_in[3];
    const int*   idx    = (const int*)  d_in[4];
    const float* W_att1 = (const float*)d_in[5];
    const float* b_att1 = (const float*)d_in[6];
    const float* W_att2 = (const float*)d_in[7];
    const float* b_att2 = (const float*)d_in[8];
    const float* W_fun1 = (const float*)d_in[9];
    const float* b_fun1 = (const float*)d_in[10];
    const float* W_fun2 = (const float*)d_in[11];
    const float* b_fun2 = (const float*)d_in[12];
    const float* conv1w = (const float*)d_in[13];
    const float* conv1b = (const float*)d_in[14];
    const float* conv2w = (const float*)d_in[15];
    const float* conv2b = (const float*)d_in[16];
    const float* W_out  = (const float*)d_in[17];
    const float* b_out  = (const float*)d_in[18];
    float* out = (float*)d_out;

    float *h_att, *h_fun, *e, *part, *part2, *fun_pack;
    cudaGetSymbolAddress((void**)&h_att, g_h_att);
    cudaGetSymbolAddress((void**)&h_fun, g_h_fun);
    cudaGetSymbolAddress((void**)&e,     g_e);
    cudaGetSymbolAddress((void**)&part,  g_part);
    cudaGetSymbolAddress((void**)&part2, g_part2);
    cudaGetSymbolAddress((void**)&fun_pack, g_fun_pack);

    // persistent side streams + events (host infra; created once, reused)
    static cudaStream_t sA = 0, sF = 0;
    static cudaEvent_t evFork = 0, evA = 0, evF = 0;
    if (!sA) {
        cudaStreamCreateWithFlags(&sA, cudaStreamNonBlocking);
        cudaStreamCreateWithFlags(&sF, cudaStreamNonBlocking);
        cudaEventCreateWithFlags(&evFork, cudaEventDisableTiming);
        cudaEventCreateWithFlags(&evA,    cudaEventDisableTiming);
        cudaEventCreateWithFlags(&evF,    cudaEventDisableTiming);
    }

    const int smem128 = gemm_smem_bytes(128);   // 62208 B
    const int smem64  = gemm_smem_bytes(64);    // 43776 B
    static bool attrSet = false;
    if (!attrSet) {
        cudaFuncSetAttribute(mma_gemm<128, 0>,
            cudaFuncAttributeMaxDynamicSharedMemorySize, smem128);
        cudaFuncSetAttribute(pair_kernel,
            cudaFuncAttributeMaxDynamicSharedMemorySize, SM_TOTAL * 4);
        attrSet = true;
    }

    const int epBlocks = (MROWS * 256 + 255) / 256;

    // ---- fork from the (captured) default stream ----
    cudaEventRecord(evFork, 0);
    cudaStreamWaitEvent(sA, evFork, 0);
    cudaStreamWaitEvent(sF, evFork, 0);

    // ===== att chain on sA =====
    mma_gemm<128, 0><<<dim3(2048 / 128, (MROWS + 127) / 128), 256, smem128, sA>>>(
        r_att, p_att, N_R, MROWS, 2048, SIZE_R, SIZE_R,
        W_att1, b_att1, h_att, 2048, 0);
    mma_gemm<64, 2><<<dim3(2, (MROWS + 63) / 64, SPLITK), 256, smem64, sA>>>(
        h_att, h_att, MROWS, MROWS, 256, 2048, 2048,
        W_att2, 0, part2, 256, 512);
    splitk_epilogue<<<epBlocks, 256, 0, sA>>>(part2, b_att2, e, out, 0);
    cudaEventRecord(evA, sA);

    // ===== fun chain on sF =====
    repack_fun<<<dim3((FUN_IN + 255) / 256, MROWS), 256, 0, sF>>>(r_fun, p_fun, fun_pack);
    mma_gemm<128, 0><<<dim3(4096 / 128, (MROWS + 127) / 128), 256, smem128, sF>>>(
        fun_pack, fun_pack, MROWS, MROWS, 4096, FUN_IN, FUN_PAD,
        W_fun1, b_fun1, h_fun, 4096, 0);
    mma_gemm<64, 2><<<dim3(2, (MROWS + 63) / 64, SPLITK), 256, smem64, sF>>>(
        h_fun, h_fun, MROWS, MROWS, 256, 4096, 4096,
        W_fun2, 0, part, 256, 1024);
    splitk_epilogue<<<epBlocks, 256, 0, sF>>>(part, b_fun2, e, out, 256);
    cudaEventRecord(evF, sF);

    // ---- join back to default stream ----
    cudaStreamWaitEvent(0, evA, 0);
    cudaStreamWaitEvent(0, evF, 0);

    // pair head (needs both halves of e)
    pair_kernel<<<NB, 256, SM_TOTAL * 4>>>(
        e, idx, conv1w, conv1b, conv2w, conv2b, W_out, b_out, out);
}

// round 17
// speedup vs baseline: 1.4199x; 1.2370x over previous
#include <cuda_runtime.h>
#include <math.h>
#include <stdint.h>

// ---------------- problem constants ----------------
#define N_R     2000
#define N_P     1512
#define MROWS   3512            // N_R + N_P
#define SIZE_R  3000
#define FUN_IN  5603
#define NB      8192
#define PROTEIN 1512

#define ATT_KW  1500            // SIZE_R/2 words
#define FUN_KW  2816            // ceil(FUN_IN/2) padded to %4
#define H1_KW   1024            // 2048/2
#define H2_KW   2048            // 4096/2

// d_out layout: e_r [2000,512] | e_p [1512,512] | output [8192,2] | flat [8192,8192]
#define E_P_OFF   1024000
#define OUT_OFF   1798144
#define FLAT_OFF  1814528

#define SPLITK 4

// smem strides (words)
#define ASTR 24
#define BSTR 132

// ---------------- device scratch (no allocs allowed) ----------------
__device__ uint32_t g_attA[MROWS * ATT_KW];       // fp16x2 A for G1
__device__ uint32_t g_funA[MROWS * FUN_KW];       // fp16x2 A for G3
__device__ uint32_t g_W1att[ATT_KW * 2048];       // fp16x2 word B [k2][n]
__device__ uint32_t g_W1fun[FUN_KW * 4096];
__device__ uint32_t g_W2att[H1_KW * 256];
__device__ uint32_t g_W2fun[H2_KW * 256];
__device__ uint32_t g_hatt[MROWS * H1_KW];        // fp16x2 h_att (G2's A)
__device__ uint32_t g_hfun[MROWS * H2_KW];        // fp16x2 h_fun (G4's A)
__device__ float g_e[MROWS * 512];
__device__ float g_part[SPLITK * MROWS * 256];
__device__ float g_part2[SPLITK * MROWS * 256];

// ---------------- helpers ----------------
typedef unsigned long long ull;

__device__ __forceinline__ uint32_t f2h2(float lo, float hi) {
    uint32_t r;
    asm("cvt.rn.f16x2.f32 %0, %1, %2;" : "=r"(r) : "f"(hi), "f"(lo));
    return r;
}

__device__ __forceinline__ void mma_f16(float c[4],
    uint32_t a0, uint32_t a1, uint32_t a2, uint32_t a3,
    uint32_t b0, uint32_t b1)
{
    asm volatile(
        "mma.sync.aligned.m16n8k16.row.col.f32.f16.f16.f32 "
        "{%0,%1,%2,%3}, {%4,%5,%6,%7}, {%8,%9}, {%0,%1,%2,%3};\n"
        : "+f"(c[0]), "+f"(c[1]), "+f"(c[2]), "+f"(c[3])
        : "r"(a0), "r"(a1), "r"(a2), "r"(a3), "r"(b0), "r"(b1));
}

__device__ __forceinline__ void cp16(uint32_t dst, const void* src, int srcBytes) {
    asm volatile("cp.async.cg.shared.global [%0], [%1], 16, %2;\n"
                 :: "r"(dst), "l"(src), "r"(srcBytes));
}
__device__ __forceinline__ void cp_commit() {
    asm volatile("cp.async.commit_group;\n" ::);
}
template<int W> __device__ __forceinline__ void cp_wait() {
    asm volatile("cp.async.wait_group %0;\n" :: "n"(W));
}

__device__ __forceinline__ ull pk(float lo, float hi) {
    ull r; asm("mov.b64 %0, {%1, %2};" : "=l"(r) : "f"(lo), "f"(hi)); return r;
}
__device__ __forceinline__ void upk(ull v, float& lo, float& hi) {
    asm("mov.b64 {%0, %1}, %2;" : "=f"(lo), "=f"(hi) : "l"(v));
}
__device__ __forceinline__ ull fma2(ull a, ull b, ull c) {
    ull d; asm("fma.rn.f32x2 %0, %1, %2, %3;" : "=l"(d) : "l"(a), "l"(b), "l"(c)); return d;
}

// ---------------- conversion kernels ----------------
// A: two-part f32 rows -> packed fp16 word matrix [MROWS][KW]
__global__ void __launch_bounds__(256) cvt_A(
    const float* __restrict__ A0, const float* __restrict__ A1, int split,
    int K, int KW, uint32_t* __restrict__ dst)
{
    int row = blockIdx.y;
    int c2 = blockIdx.x * 256 + threadIdx.x;
    if (c2 >= KW) return;
    const float* src = (row < split) ? (A0 + (size_t)row * K)
                                     : (A1 + (size_t)(row - split) * K);
    int k = 2 * c2;
    float lo = (k < K) ? src[k] : 0.0f;
    float hi = (k + 1 < K) ? src[k + 1] : 0.0f;
    dst[(size_t)row * KW + c2] = f2h2(lo, hi);
}

// B: f32 [K][N] -> interleaved fp16 word matrix [KW][N], word = (B[2k2][n], B[2k2+1][n])
__global__ void __launch_bounds__(256) cvt_B(
    const float* __restrict__ src, int K, int N, int KW, uint32_t* __restrict__ dst)
{
    size_t i = (size_t)blockIdx.x * 256 + threadIdx.x;
    if (i >= (size_t)KW * N) return;
    int k2 = (int)(i / N);
    int n  = (int)(i % N);
    int k = 2 * k2;
    float lo = (k < K) ? src[(size_t)k * N + n] : 0.0f;
    float hi = (k + 1 < K) ? src[(size_t)(k + 1) * N + n] : 0.0f;
    dst[i] = f2h2(lo, hi);
}

// ---------------- FP16 tensor-core GEMM, 3-stage cp.async pipeline ----------------
// All K addressing in 32-bit words (= fp16 pairs). Fragment word-indices are
// identical to the tf32 version (logical word t <-> phys 2t, t+4 <-> 2t+1).
// MODE 0: gelu(exact) -> Cw fp16 word matrix [M][N/2], full KW.
// MODE 2: raw f32 partial -> Cp + blockIdx.z*M*256, word slice [z*kslW, ...).
template<int BM, int MODE>
__global__ void __launch_bounds__(256, 2) mma_gemm_h(
    const uint32_t* __restrict__ A0, const uint32_t* __restrict__ A1, int split,
    int M, int N, int KW, int ldaw,
    const uint32_t* __restrict__ B, const float* __restrict__ bias,
    uint32_t* __restrict__ Cw, int ldcw,
    float* __restrict__ Cpart, int kslW)
{
    constexpr int BN = 128;
    constexpr int BKW = 16;
    constexpr int MT = BM / 32;
    constexpr int AF = (BM * BKW) / (4 * 256);

    extern __shared__ uint32_t smemU[];
    uint32_t* As = smemU;                      // [3][BM][ASTR]
    uint32_t* Bs = smemU + 3 * BM * ASTR;      // [3][BKW][BSTR]

    const int tid  = threadIdx.x;
    const int lane = tid & 31;
    const int warp = tid >> 5;
    const int wr = warp & 1;
    const int wc = warp >> 1;
    const int g = lane >> 2;
    const int t = lane & 3;

    const int rowBase = blockIdx.y * BM;
    const int colBase = blockIdx.x * BN;
    const int wm = wr * (BM / 2);
    const int wn = wc * 32;

    int kbeg = 0, kend = KW;
    if (MODE == 2) { kbeg = blockIdx.z * kslW; kend = min(KW, kbeg + kslW); }
    float* Cp = Cpart;
    if (MODE == 2) Cp = Cpart + (size_t)blockIdx.z * M * 256;

    float acc[MT][4][4];
#pragma unroll
    for (int i = 0; i < MT; i++)
#pragma unroll
        for (int j = 0; j < 4; j++)
#pragma unroll
            for (int q = 0; q < 4; q++) acc[i][j][q] = 0.0f;

    const uint32_t* Arow[AF];
#pragma unroll
    for (int i = 0; i < AF; i++) {
        int f = tid + i * 256;
        int m = f >> 2;
        int row = rowBase + m;
        Arow[i] = 0;
        if (row < M)
            Arow[i] = (row < split) ? (A0 + (size_t)row * ldaw)
                                    : (A1 + (size_t)(row - split) * ldaw);
    }

    const uint32_t AsAddr = (uint32_t)__cvta_generic_to_shared(As);
    const uint32_t BsAddr = (uint32_t)__cvta_generic_to_shared(Bs);

    const int nIter = (kend - kbeg + BKW - 1) / BKW;

    auto issueTile = [&](int it, int buf) {
        int k0 = kbeg + it * BKW;
#pragma unroll
        for (int i = 0; i < AF; i++) {
            int f = tid + i * 256;
            int m = f >> 2;
            int kq = f & 3;
            int k = k0 + kq * 4;
            uint32_t dst = AsAddr + (uint32_t)((((buf * BM + m) * ASTR) + kq * 4) * 4);
            int bytes = 0;
            if (Arow[i]) { bytes = (kend - k) * 4; bytes = bytes < 0 ? 0 : (bytes > 16 ? 16 : bytes); }
            cp16(dst, Arow[i] ? (Arow[i] + k) : A0, bytes);
        }
#pragma unroll
        for (int i = 0; i < 2; i++) {
            int f = tid + i * 256;
            int kk = f >> 5;
            int nq = f & 31;
            int krow = k0 + kk;
            uint32_t dst = BsAddr + (uint32_t)((((buf * BKW + kk) * BSTR) + nq * 4) * 4);
            int kc = krow < KW - 1 ? krow : KW - 1;
            const uint32_t* src = B + (size_t)kc * N + colBase + nq * 4;
            cp16(dst, src, krow < kend ? 16 : 0);
        }
        cp_commit();
    };

    issueTile(0, 0);
    if (nIter > 1) issueTile(1, 1);

    int buf = 0;
    for (int it = 0; it < nIter; it++) {
        if (it + 1 < nIter) cp_wait<1>(); else cp_wait<0>();
        __syncthreads();

#pragma unroll
        for (int ks = 0; ks < 2; ks++) {
            uint32_t afr[MT][4];
            uint32_t bfr[4][2];
#pragma unroll
            for (int mt = 0; mt < MT; mt++) {
                int r0 = wm + mt * 16 + g;
                const uint32_t* pa = As + (buf * BM + r0) * ASTR + ks * 8 + 2 * t;
                uint2 va = *(const uint2*)pa;
                uint2 vb = *(const uint2*)(pa + 8 * ASTR);
                afr[mt][0] = va.x;   // word (g,   wt)
                afr[mt][1] = vb.x;   // word (g+8, wt)
                afr[mt][2] = va.y;   // word (g,   wt+4)
                afr[mt][3] = vb.y;   // word (g+8, wt+4)
            }
#pragma unroll
            for (int nt = 0; nt < 4; nt++) {
                int c0 = wn + nt * 8 + g;
                const uint32_t* pb = Bs + (buf * BKW + ks * 8 + 2 * t) * BSTR + c0;
                bfr[nt][0] = pb[0];      // word row wt   (k=2t..2t+1)
                bfr[nt][1] = pb[BSTR];   // word row wt+4 (k=2t+8..2t+9)
            }
#pragma unroll
            for (int mt = 0; mt < MT; mt++)
#pragma unroll
                for (int nt = 0; nt < 4; nt++)
                    mma_f16(acc[mt][nt],
                            afr[mt][0], afr[mt][1], afr[mt][2], afr[mt][3],
                            bfr[nt][0], bfr[nt][1]);
        }
        __syncthreads();

        if (it + 2 < nIter) issueTile(it + 2, (it + 2) % 3);
        buf = (buf + 1 == 3) ? 0 : buf + 1;
    }

    // ---- epilogue ----
#pragma unroll
    for (int mt = 0; mt < MT; mt++) {
#pragma unroll
        for (int rh = 0; rh < 2; rh++) {
            int r = rowBase + wm + mt * 16 + g + rh * 8;
            if (r >= M) continue;
#pragma unroll
            for (int nt = 0; nt < 4; nt++) {
                int cbase = colBase + wn + nt * 8;
                if (MODE == 0) {
                    int c0 = cbase + 2 * t;
                    float v0 = acc[mt][nt][rh * 2 + 0] + bias[c0];
                    float v1 = acc[mt][nt][rh * 2 + 1] + bias[c0 + 1];
                    v0 = 0.5f * v0 * (1.0f + erff(v0 * 0.70710678118654752f));
                    v1 = 0.5f * v1 * (1.0f + erff(v1 * 0.70710678118654752f));
                    Cw[(size_t)r * ldcw + (cbase >> 1) + t] = f2h2(v0, v1);
                } else {
#pragma unroll
                    for (int cj = 0; cj < 2; cj++) {
                        int c = cbase + 2 * t + cj;
                        Cp[(size_t)r * 256 + c] = acc[mt][nt][rh * 2 + cj];
                    }
                }
            }
        }
    }
}

static inline int gemm_smem_bytes(int BM) {
    return (3 * BM * ASTR + 3 * 16 * BSTR) * 4;
}

// ---------------- split-K reduce + bias + sigmoid + scatter ----------------
__global__ void __launch_bounds__(256) splitk_epilogue(
    const float* __restrict__ part, const float* __restrict__ bias,
    float* __restrict__ ebuf, float* __restrict__ dout, int ecol)
{
    int i = blockIdx.x * 256 + threadIdx.x;
    int r = i >> 8;
    int c = i & 255;
    if (r >= MROWS) return;
    float v = part[i];
#pragma unroll
    for (int s = 1; s < SPLITK; s++) v += part[i + (size_t)s * MROWS * 256];
    v = 1.0f / (1.0f + expf(-(v + bias[c])));
    ebuf[(size_t)r * 512 + ecol + c] = v;
    if (r < N_R)
        dout[(size_t)r * 512 + ecol + c] = v;
    else
        dout[(size_t)E_P_OFF + (size_t)(r - N_R) * 512 + ecol + c] = v;
}

// ---------------- pair kernel (unchanged) ----------------
#define SM_XP    0
#define SM_H1P   3120
#define SM_SW2   (3120 + 8448)
#define SM_SW1   (3120 + 8448 + 7680)
#define SM_BRED  (3120 + 8448 + 7680 + 240)
#define SM_TOTAL (3120 + 8448 + 7680 + 240 + 16)

template<int S, int RR, int IH>
__device__ __forceinline__ void combo(
    ull accp[2][2][4], const ull wp[2][2][5], const ull hp[2][11])
{
#pragma unroll
    for (int jp = 0; jp < 4; jp++)
#pragma unroll
        for (int kw = 0; kw < 5; kw++) {
            accp[0][RR][jp] = fma2(wp[0][S][kw], hp[IH][2 * jp + kw], accp[0][RR][jp]);
            accp[1][RR][jp] = fma2(wp[1][S][kw], hp[IH][2 * jp + kw], accp[1][RR][jp]);
        }
}

__global__ void __launch_bounds__(256) pair_kernel(
    const float* __restrict__ e, const int* __restrict__ idx,
    const float* __restrict__ w1, const float* __restrict__ b1,
    const float* __restrict__ w2, const float* __restrict__ b2,
    const float* __restrict__ Wout, const float* __restrict__ bout,
    float* __restrict__ dout)
{
    extern __shared__ float sm[];
    float* xp   = sm + SM_XP;
    float* h1p  = sm + SM_H1P;
    float* sw2  = sm + SM_SW2;
    float* sw1  = sm + SM_SW1;
    float* bred = sm + SM_BRED;

    const int tid = threadIdx.x;
    const int b = blockIdx.x;

    const int iv = idx[b];
    const int rno = iv / PROTEIN;
    const int pno = iv % PROTEIN;
    const float* er = e + (size_t)rno * 512;
    const float* ep = e + (size_t)(N_R + pno) * 512;

    for (int i = tid; i < 6 * 520; i += 256) xp[i] = 0.0f;
    for (int i = tid; i < 16 * 2 * 264; i += 256) h1p[i] = 0.0f;
    for (int i = tid; i < 240; i += 256) sw1[i] = w1[i];
    for (int i = tid; i < 7680; i += 256) sw2[i] = w2[i];
    for (int w = tid; w < 512; w += 256) {
        xp[2 * 520 + 4 + w] = er[w];
        xp[3 * 520 + 4 + w] = ep[w];
    }
    __syncthreads();

    for (int id = tid; id < 16 * 2 * 256; id += 256) {
        int c  = id >> 9;
        int rm = id & 511;
        int ph = rm >> 8;
        int pw = rm & 255;
        float wv[15];
#pragma unroll
        for (int q = 0; q < 15; q++) wv[q] = sw1[c * 15 + q];
        float bb = b1[c];
        float sum = 0.0f;
#pragma unroll
        for (int oh2 = 0; oh2 < 2; oh2++) {
#pragma unroll
            for (int ow2 = 0; ow2 < 2; ow2++) {
                int oh = 2 * ph + oh2;
                int ow = 2 * pw + ow2;
                float v = bb;
#pragma unroll
                for (int kh = 0; kh < 3; kh++) {
                    const float* xr = xp + (oh + kh) * 520 + (ow + 2);
#pragma unroll
                    for (int kw = 0; kw < 5; kw++)
                        v = fmaf(wv[kh * 5 + kw], xr[kw], v);
                }
                sum += (v >= 0.0f) ? v : 0.01f * v;
            }
        }
        h1p[(c * 2 + ph) * 264 + 4 + pw] = 0.25f * sum;
    }
    __syncthreads();

    float a0 = 0.0f, a1 = 0.0f;

    for (int tt = 0; tt < 4; tt++) {
        int task = tt * 256 + tid;
        int ocp = task >> 6;
        int ph  = (task >> 5) & 1;
        int pwg = task & 31;
        int oc0 = ocp * 2;
        int w0 = pwg * 8;

        ull accp[2][2][4];
#pragma unroll
        for (int o = 0; o < 2; o++)
#pragma unroll
            for (int r = 0; r < 2; r++)
#pragma unroll
                for (int jp = 0; jp < 4; jp++) accp[o][r][jp] = 0ull;

        const int khA = ph ? 0 : 1;

        for (int ic = 0; ic < 16; ic++) {
            ull hp[2][11];
#pragma unroll
            for (int ih = 0; ih < 2; ih++) {
                const float* row = h1p + (ic * 2 + ih) * 264;
                float hv[16];
                float4 q0 = *(const float4*)(row + w0);
                float4 q1 = *(const float4*)(row + w0 + 4);
                float4 q2 = *(const float4*)(row + w0 + 8);
                float4 q3 = *(const float4*)(row + w0 + 12);
                hv[0]=q0.x; hv[1]=q0.y; hv[2]=q0.z; hv[3]=q0.w;
                hv[4]=q1.x; hv[5]=q1.y; hv[6]=q1.z; hv[7]=q1.w;
                hv[8]=q2.x; hv[9]=q2.y; hv[10]=q2.z; hv[11]=q2.w;
                hv[12]=q3.x; hv[13]=q3.y; hv[14]=q3.z; hv[15]=q3.w;
#pragma unroll
                for (int m = 0; m < 11; m++) hp[ih][m] = pk(hv[2 + m], hv[3 + m]);
            }
            ull wp[2][2][5];
#pragma unroll
            for (int o = 0; o < 2; o++)
#pragma unroll
                for (int s = 0; s < 2; s++)
#pragma unroll
                    for (int kw = 0; kw < 5; kw++) {
                        float w = sw2[((oc0 + o) * 16 + ic) * 15 + (khA + s) * 5 + kw];
                        wp[o][s][kw] = pk(w, w);
                    }

            if (ph == 0) {
                combo<1, 0, 0>(accp, wp, hp);
                combo<0, 1, 0>(accp, wp, hp);
                combo<1, 1, 1>(accp, wp, hp);
            } else {
                combo<0, 0, 0>(accp, wp, hp);
                combo<1, 0, 1>(accp, wp, hp);
                combo<0, 1, 1>(accp, wp, hp);
            }
        }

#pragma unroll
        for (int o = 0; o < 2; o++) {
            int oc = oc0 + o;
            float bb = b2[oc];
            int fibase = oc * 256 + ph * 128 + pwg * 4;
            float4 fv4;
            float fvs[4];
#pragma unroll
            for (int jp = 0; jp < 4; jp++) {
                float v00, v01, v10, v11;
                upk(accp[o][0][jp], v00, v01);
                upk(accp[o][1][jp], v10, v11);
                v00 += bb; v01 += bb; v10 += bb; v11 += bb;
                v00 = (v00 >= 0.0f) ? v00 : 0.01f * v00;
                v01 = (v01 >= 0.0f) ? v01 : 0.01f * v01;
                v10 = (v10 >= 0.0f) ? v10 : 0.01f * v10;
                v11 = (v11 >= 0.0f) ? v11 : 0.01f * v11;
                float m = fmaxf(fmaxf(v00, v01), fmaxf(v10, v11));
                float fv = tanhf(m);
                fvs[jp] = fv;
                int fi = fibase + jp;
                a0 = fmaf(fv, __ldg(&Wout[2 * fi]), a0);
                a1 = fmaf(fv, __ldg(&Wout[2 * fi + 1]), a1);
            }
            fv4.x = fvs[0]; fv4.y = fvs[1]; fv4.z = fvs[2]; fv4.w = fvs[3];
            *(float4*)(dout + (size_t)FLAT_OFF + (size_t)b * 8192 + fibase) = fv4;
        }
    }

#pragma unroll
    for (int off = 16; off > 0; off >>= 1) {
        a0 += __shfl_down_sync(0xFFFFFFFFu, a0, off);
        a1 += __shfl_down_sync(0xFFFFFFFFu, a1, off);
    }
    if ((tid & 31) == 0) {
        bred[(tid >> 5) * 2 + 0] = a0;
        bred[(tid >> 5) * 2 + 1] = a1;
    }
    __syncthreads();
    if (tid == 0) {
        float s0 = bout[0], s1 = bout[1];
#pragma unroll
        for (int w = 0; w < 8; w++) { s0 += bred[2 * w]; s1 += bred[2 * w + 1]; }
        dout[(size_t)OUT_OFF + (size_t)b * 2 + 0] = s0;
        dout[(size_t)OUT_OFF + (size_t)b * 2 + 1] = s1;
    }
}

// ---------------- launcher ----------------
extern "C" void kernel_launch(void* const* d_in, const int* in_sizes, int n_in,
                              void* d_out, int out_size)
{
    const float* r_att  = (const float*)d_in[0];
    const float* p_att  = (const float*)d_in[1];
    const float* r_fun  = (const float*)d_in[2];
    const float* p_fun  = (const float*)d_in[3];
    const int*   idx    = (const int*)  d_in[4];
    const float* W_att1 = (const float*)d_in[5];
    const float* b_att1 = (const float*)d_in[6];
    const float* W_att2 = (const float*)d_in[7];
    const float* b_att2 = (const float*)d_in[8];
    const float* W_fun1 = (const float*)d_in[9];
    const float* b_fun1 = (const float*)d_in[10];
    const float* W_fun2 = (const float*)d_in[11];
    const float* b_fun2 = (const float*)d_in[12];
    const float* conv1w = (const float*)d_in[13];
    const float* conv1b = (const float*)d_in[14];
    const float* conv2w = (const float*)d_in[15];
    const float* conv2b = (const float*)d_in[16];
    const float* W_out  = (const float*)d_in[17];
    const float* b_out  = (const float*)d_in[18];
    float* out = (float*)d_out;

    uint32_t *attA, *funA, *W1a, *W1f, *W2a, *W2f, *hatt, *hfun;
    float *e, *part, *part2;
    cudaGetSymbolAddress((void**)&attA, g_attA);
    cudaGetSymbolAddress((void**)&funA, g_funA);
    cudaGetSymbolAddress((void**)&W1a,  g_W1att);
    cudaGetSymbolAddress((void**)&W1f,  g_W1fun);
    cudaGetSymbolAddress((void**)&W2a,  g_W2att);
    cudaGetSymbolAddress((void**)&W2f,  g_W2fun);
    cudaGetSymbolAddress((void**)&hatt, g_hatt);
    cudaGetSymbolAddress((void**)&hfun, g_hfun);
    cudaGetSymbolAddress((void**)&e,     g_e);
    cudaGetSymbolAddress((void**)&part,  g_part);
    cudaGetSymbolAddress((void**)&part2, g_part2);

    static cudaStream_t sA = 0, sF = 0;
    static cudaEvent_t evFork = 0, evA = 0, evF = 0;
    if (!sA) {
        cudaStreamCreateWithFlags(&sA, cudaStreamNonBlocking);
        cudaStreamCreateWithFlags(&sF, cudaStreamNonBlocking);
        cudaEventCreateWithFlags(&evFork, cudaEventDisableTiming);
        cudaEventCreateWithFlags(&evA,    cudaEventDisableTiming);
        cudaEventCreateWithFlags(&evF,    cudaEventDisableTiming);
    }

    const int smem128 = gemm_smem_bytes(128);
    const int smem64  = gemm_smem_bytes(64);
    static bool attrSet = false;
    if (!attrSet) {
        cudaFuncSetAttribute(mma_gemm_h<128, 0>,
            cudaFuncAttributeMaxDynamicSharedMemorySize, smem128);
        cudaFuncSetAttribute(pair_kernel,
            cudaFuncAttributeMaxDynamicSharedMemorySize, SM_TOTAL * 4);
        attrSet = true;
    }

    const int epBlocks = (MROWS * 256 + 255) / 256;

    // ---- fork ----
    cudaEventRecord(evFork, 0);
    cudaStreamWaitEvent(sA, evFork, 0);
    cudaStreamWaitEvent(sF, evFork, 0);

    // ===== att chain on sA =====
    cvt_A<<<dim3((ATT_KW + 255) / 256, MROWS), 256, 0, sA>>>(
        r_att, p_att, N_R, SIZE_R, ATT_KW, attA);
    cvt_B<<<(int)(((size_t)ATT_KW * 2048 + 255) / 256), 256, 0, sA>>>(
        W_att1, SIZE_R, 2048, ATT_KW, W1a);
    cvt_B<<<(int)(((size_t)H1_KW * 256 + 255) / 256), 256, 0, sA>>>(
        W_att2, 2048, 256, H1_KW, W2a);
    mma_gemm_h<128, 0><<<dim3(2048 / 128, (MROWS + 127) / 128), 256, smem128, sA>>>(
        attA, attA, MROWS, MROWS, 2048, ATT_KW, ATT_KW,
        W1a, b_att1, hatt, H1_KW, 0, 0);
    mma_gemm_h<64, 2><<<dim3(2, (MROWS + 63) / 64, SPLITK), 256, smem64, sA>>>(
        hatt, hatt, MROWS, MROWS, 256, H1_KW, H1_KW,
        W2a, 0, 0, 0, part2, H1_KW / SPLITK);
    splitk_epilogue<<<epBlocks, 256, 0, sA>>>(part2, b_att2, e, out, 0);
    cudaEventRecord(evA, sA);

    // ===== fun chain on sF =====
    cvt_A<<<dim3((FUN_KW + 255) / 256, MROWS), 256, 0, sF>>>(
        r_fun, p_fun, N_R, FUN_IN, FUN_KW, funA);
    cvt_B<<<(int)(((size_t)FUN_KW * 4096 + 255) / 256), 256, 0, sF>>>(
        W_fun1, FUN_IN, 4096, FUN_KW, W1f);
    cvt_B<<<(int)(((size_t)H2_KW * 256 + 255) / 256), 256, 0, sF>>>(
        W_fun2, 4096, 256, H2_KW, W2f);
    mma_gemm_h<128, 0><<<dim3(4096 / 128, (MROWS + 127) / 128), 256, smem128, sF>>>(
        funA, funA, MROWS, MROWS, 4096, FUN_KW, FUN_KW,
        W1f, b_fun1, hfun, H2_KW, 0, 0);
    mma_gemm_h<64, 2><<<dim3(2, (MROWS + 63) / 64, SPLITK), 256, smem64, sF>>>(
        hfun, hfun, MROWS, MROWS, 256, H2_KW, H2_KW,
        W2f, 0, 0, 0, part, H2_KW / SPLITK);
    splitk_epilogue<<<epBlocks, 256, 0, sF>>>(part, b_fun2, e, out, 256);
    cudaEventRecord(evF, sF);

    // ---- join ----
    cudaStreamWaitEvent(0, evA, 0);
    cudaStreamWaitEvent(0, evF, 0);

    // pair head
    pair_kernel<<<NB, 256, SM_TOTAL * 4>>>(
        e, idx, conv1w, conv1b, conv2w, conv2b, W_out, b_out, out);
}